// round 14
// baseline (speedup 1.0000x reference)
#include <cuda_runtime.h>
#include <cuda_fp16.h>
#include <cstdint>
#include <math.h>

#define N_RAYS 4096
#define N_SAMPLES 192
#define GRID_D 160
#define GRID_D2 (160*160)
#define GRID_D3 (160*160*160)
#define K0_DIM 12
#define XYZ_MIN (-1.2f)
#define COORD_SCALE (159.0f / 2.4f)
#define ACT_SHIFT (-4.595119850134589f)
#define STEPDIST (2.8f / 192.0f)
#define NEARV 0.2f
#define FARV 3.0f

#define NPTS (N_RAYS * N_SAMPLES)
#define BLOCK 256
#define NTILES (NPTS / BLOCK)      /* 3072 */
#define GRID_P 296                 /* 2 CTAs x 148 SMs persistent */

// ---------------- scratch ----------------
__device__ float g_alpha[NPTS];
__device__ float g_rgb0[NPTS];
__device__ float g_rgb1[NPTS];
__device__ float g_rgb2[NPTS];
__device__ uint32_t PW0T[128 * 28];    // [n][kpair] bf16x2, k<39 real (pad 48)
__device__ uint32_t PW1T8[128 * 36];   // [n][kquad] e4m3x4, k<128 real (stride 36 words)
// packed voxel: 16B = [density bf16 | k0[0..11] e4m3 | pad16]
__device__ uint4 PG[GRID_D3];          // 65.5 MB (L2-resident)

// ---------------- smem layout (4-byte word units) ----------------
#define SM_W0T  0                      /* 3584 */
#define SM_W1T8 3584                   /* 4608 */
#define SM_F    8192                   /* 256*28 = 7168 */
#define SM_W2   15360                  /* 384 */
#define SM_B0   15744
#define SM_B1   15872
#define SM_B2   16000                  /* 4 */
#define SM_G    16004                  /* gather buf: 8 x 256 x uint4 = 8192 words; byte off 64016 %16==0 */
#define SM_WORDS (SM_G + 8192)
#define SMEM_BYTES (SM_WORDS * 4)      /* ~94.5 KB -> 2 CTAs/SM */

__device__ __forceinline__ uint32_t pack_bf16x2(float lo, float hi) {
    uint32_t u;
    asm("cvt.rn.bf16x2.f32 %0, %1, %2;" : "=r"(u) : "f"(hi), "f"(lo));
    return u;
}
__device__ __forceinline__ float bflo(uint32_t u) { return __uint_as_float(u << 16); }

__device__ __forceinline__ uint32_t pack_e4m3x2(float lo, float hi) {
    uint16_t r;
    asm("cvt.rn.satfinite.e4m3x2.f32 %0, %1, %2;" : "=h"(r) : "f"(hi), "f"(lo));
    return (uint32_t)r;
}
__device__ __forceinline__ __half2 e4m3x2_to_h2(uint32_t u) {
    uint32_t h2;
    asm("cvt.rn.f16x2.e4m3x2 %0, %1;" : "=r"(h2) : "h"((uint16_t)(u)));
    return *reinterpret_cast<__half2*>(&h2);
}

__device__ __forceinline__ uint32_t smem_u32(const void* p) {
    uint32_t a;
    asm("{ .reg .u64 t; cvta.to.shared.u64 t, %1; cvt.u32.u64 %0, t; }" : "=r"(a) : "l"(p));
    return a;
}
__device__ __forceinline__ void ldsm_x4(uint32_t& r0, uint32_t& r1, uint32_t& r2, uint32_t& r3,
                                        uint32_t addr) {
    asm volatile("ldmatrix.sync.aligned.m8n8.x4.shared.b16 {%0,%1,%2,%3}, [%4];"
                 : "=r"(r0), "=r"(r1), "=r"(r2), "=r"(r3) : "r"(addr));
}
__device__ __forceinline__ void ldsm_x2(uint32_t& r0, uint32_t& r1, uint32_t addr) {
    asm volatile("ldmatrix.sync.aligned.m8n8.x2.shared.b16 {%0,%1}, [%2];"
                 : "=r"(r0), "=r"(r1) : "r"(addr));
}
__device__ __forceinline__ void mma_bf16(float c[4],
                                         uint32_t a0, uint32_t a1, uint32_t a2, uint32_t a3,
                                         uint32_t b0, uint32_t b1) {
    asm volatile("mma.sync.aligned.m16n8k16.row.col.f32.bf16.bf16.f32 "
                 "{%0,%1,%2,%3}, {%4,%5,%6,%7}, {%8,%9}, {%0,%1,%2,%3};"
                 : "+f"(c[0]), "+f"(c[1]), "+f"(c[2]), "+f"(c[3])
                 : "r"(a0), "r"(a1), "r"(a2), "r"(a3), "r"(b0), "r"(b1));
}
__device__ __forceinline__ void mma_fp8(float c[4],
                                        uint32_t a0, uint32_t a1, uint32_t a2, uint32_t a3,
                                        uint32_t b0, uint32_t b1) {
    asm volatile("mma.sync.aligned.m16n8k32.row.col.f32.e4m3.e4m3.f32 "
                 "{%0,%1,%2,%3}, {%4,%5,%6,%7}, {%8,%9}, {%0,%1,%2,%3};"
                 : "+f"(c[0]), "+f"(c[1]), "+f"(c[2]), "+f"(c[3])
                 : "r"(a0), "r"(a1), "r"(a2), "r"(a3), "r"(b0), "r"(b1));
}
#define CP_ASYNC16(dst, src) \
    asm volatile("cp.async.cg.shared.global [%0], [%1], 16;" :: "r"(dst), "l"(src))
#define CP_COMMIT() asm volatile("cp.async.commit_group;" ::: "memory")
#define CP_WAIT0()  asm volatile("cp.async.wait_group 0;" ::: "memory")

// ---------------- pack grids (+ weight prep folded in) ----------------
__global__ void __launch_bounds__(256)
pack_grid_kernel(const float* __restrict__ dgrid, const float* __restrict__ k0grid,
                 const float* __restrict__ w0, const float* __restrict__ w1)
{
    const int gid = blockIdx.x * blockDim.x + threadIdx.x;
    if (gid < 128 * 28) {
        const int n = gid / 28, wd = gid - n * 28;
        const int k = 2 * wd;
        const float lo = (k < 39) ? w0[k * 128 + n] : 0.0f;
        const float hi = (k + 1 < 39) ? w0[(k + 1) * 128 + n] : 0.0f;
        PW0T[gid] = pack_bf16x2(lo, hi);
    } else if (gid < 128 * 28 + 128 * 36) {
        const int i = gid - 128 * 28;
        const int n = i / 36, wd = i - n * 36;
        const int k = 4 * wd;
        const float v0 = (k < 128) ? w1[k * 128 + n] : 0.0f;
        const float v1 = (k + 1 < 128) ? w1[(k + 1) * 128 + n] : 0.0f;
        const float v2 = (k + 2 < 128) ? w1[(k + 2) * 128 + n] : 0.0f;
        const float v3 = (k + 3 < 128) ? w1[(k + 3) * 128 + n] : 0.0f;
        PW1T8[i] = pack_e4m3x2(v0, v1) | (pack_e4m3x2(v2, v3) << 16);
    }
    const int v = gid;
    if (v >= GRID_D3) return;
    const float d = dgrid[v];
    float k[12];
#pragma unroll
    for (int c = 0; c < K0_DIM; c++) k[c] = k0grid[c * GRID_D3 + v];
    const uint32_t dbf = pack_bf16x2(d, 0.0f) & 0xffffu;
    const uint32_t a = dbf | (pack_e4m3x2(k[0], k[1]) << 16);
    const uint32_t b = pack_e4m3x2(k[2], k[3]) | (pack_e4m3x2(k[4], k[5]) << 16);
    const uint32_t c = pack_e4m3x2(k[6], k[7]) | (pack_e4m3x2(k[8], k[9]) << 16);
    const uint32_t e = pack_e4m3x2(k[10], k[11]);
    PG[v] = make_uint4(a, b, c, e);
}

// ---------------- persistent point kernel ----------------
__global__ void __launch_bounds__(BLOCK, 2)
point_kernel(const float* __restrict__ rays_o,
             const float* __restrict__ rays_d,
             const float* __restrict__ w2,
             const float* __restrict__ b0,
             const float* __restrict__ b1,
             const float* __restrict__ b2)
{
    extern __shared__ float sm[];
    uint32_t* smw = (uint32_t*)sm;
    const int tid = threadIdx.x;
    const uint32_t sm_base = smem_u32(sm);
    const uint32_t gdst0 = sm_base + SM_G * 4 + (uint32_t)tid * 16;

    // ---- stage weights ONCE per CTA ----
    {
        float4* d0 = (float4*)(smw + SM_W0T);
        const float4* s0 = (const float4*)PW0T;
        for (int i = tid; i < 896; i += BLOCK) d0[i] = s0[i];
        float4* d1 = (float4*)(smw + SM_W1T8);
        const float4* s1 = (const float4*)PW1T8;
        for (int i = tid; i < 1152; i += BLOCK) d1[i] = s1[i];
    }
    for (int i = tid; i < 384; i += BLOCK) sm[SM_W2 + i] = w2[i];
    if (tid < 128) {
        sm[SM_B0 + tid] = b0[tid];
        sm[SM_B1 + tid] = b1[tid];
    }
    if (tid < 3) sm[SM_B2 + tid] = b2[tid];

    const int lane = tid & 31;
    const int warp = tid >> 5;
    const int g8 = lane >> 2;
    const int q = lane & 3;
    const int m0 = warp * 32;
    const int arow = lane & 7;
    const int amt = lane >> 3;
    const int lrow = lane & 7;            // fp8 B ldsm row (lanes 0-15 matter)
    const int lmat = (lane >> 3) & 1;
    const uint32_t Fb  = sm_base + SM_F * 4;
    const uint32_t W0b = sm_base + SM_W0T * 4;
    const uint32_t W1b8 = sm_base + SM_W1T8 * 4;
    const uint4* gbuf = (const uint4*)(smw + SM_G);

    const bool swapq = (q == 1) || (q == 2);   // stage-2 routing lanes
    const int spar_q = q >> 1;                 // 0 for q<2, 1 for q>=2

    float wxy0, wxy1, wxy2, wxy3, ezr, fzr, pvx, pvy, pvz;
    int sidx;
    int t = blockIdx.x;

    auto issue = [&](int tt) {
        const int idx = tt * BLOCK + tid;
        const int r = idx / N_SAMPLES;
        const int s = idx - r * N_SAMPLES;
        float dx = rays_d[r * 3 + 0], dy = rays_d[r * 3 + 1], dz = rays_d[r * 3 + 2];
        const float inv = rsqrtf(dx * dx + dy * dy + dz * dz);
        const float vx = dx * inv, vy = dy * inv, vz = dz * inv;
        const float tval = NEARV + (FARV - NEARV) * ((float)s + 0.5f) / (float)N_SAMPLES;
        float px = rays_o[r * 3 + 0] + vx * tval;
        float py = rays_o[r * 3 + 1] + vy * tval;
        float pz = rays_o[r * 3 + 2] + vz * tval;
        const float nrm = fmaxf(fabsf(px), fmaxf(fabsf(py), fabsf(pz)));
        if (nrm > 1.0f) {
            const float invn = 1.0f / nrm;
            const float sc = (1.2f - 0.2f * invn) * invn;
            px *= sc; py *= sc; pz *= sc;
        }
        float gx = (px - XYZ_MIN) * COORD_SCALE;
        float gy = (py - XYZ_MIN) * COORD_SCALE;
        float gz = (pz - XYZ_MIN) * COORD_SCALE;
        gx = fminf(fmaxf(gx, 0.0f), 159.0f);
        gy = fminf(fmaxf(gy, 0.0f), 159.0f);
        gz = fminf(fmaxf(gz, 0.0f), 159.0f);
        const int ix = min((int)floorf(gx), 158);
        const int iy = min((int)floorf(gy), 158);
        const int iz = min((int)floorf(gz), 158);
        const float fx = gx - (float)ix, fy = gy - (float)iy, fz = gz - (float)iz;
        const float ex = 1.0f - fx, ey = 1.0f - fy;
        const int base = ix * GRID_D2 + iy * GRID_D + iz;
        wxy0 = ex * ey; wxy1 = ex * fy; wxy2 = fx * ey; wxy3 = fx * fy;
        ezr = 1.0f - fz; fzr = fz;
        pvx = vx; pvy = vy; pvz = vz;
        sidx = idx;
        const int vb[4] = {base, base + GRID_D, base + GRID_D2, base + GRID_D2 + GRID_D};
#pragma unroll
        for (int p = 0; p < 4; p++) {
            const char* src = (const char*)(PG + vb[p]);
            CP_ASYNC16(gdst0 + (uint32_t)(2 * p) * 4096u, src);
            CP_ASYNC16(gdst0 + (uint32_t)(2 * p + 1) * 4096u, src + 16);
        }
    };

    issue(t);
    CP_COMMIT();
    __syncthreads();

    while (true) {
        CP_WAIT0();

        // ---- decode gather buffer -> density + k0 features ----
        float accd = 0.0f;
        __half2 acck[6];
#pragma unroll
        for (int j = 0; j < 6; j++) acck[j] = __float2half2_rn(0.0f);
        {
            const float wxy[4] = {wxy0, wxy1, wxy2, wxy3};
#pragma unroll
            for (int p = 0; p < 4; p++) {
                const uint4 q0 = gbuf[(2 * p) * 256 + tid];
                const uint4 q1 = gbuf[(2 * p + 1) * 256 + tid];
                const float wz0 = wxy[p] * ezr, wz1 = wxy[p] * fzr;
                accd += bflo(q0.x) * wz0 + bflo(q1.x) * wz1;
                const __half2 h0 = __float2half2_rn(wz0);
                const __half2 h1 = __float2half2_rn(wz1);
                acck[0] = __hfma2(e4m3x2_to_h2(q0.x >> 16), h0, acck[0]);
                acck[1] = __hfma2(e4m3x2_to_h2(q0.y), h0, acck[1]);
                acck[2] = __hfma2(e4m3x2_to_h2(q0.y >> 16), h0, acck[2]);
                acck[3] = __hfma2(e4m3x2_to_h2(q0.z), h0, acck[3]);
                acck[4] = __hfma2(e4m3x2_to_h2(q0.z >> 16), h0, acck[4]);
                acck[5] = __hfma2(e4m3x2_to_h2(q0.w), h0, acck[5]);
                acck[0] = __hfma2(e4m3x2_to_h2(q1.x >> 16), h1, acck[0]);
                acck[1] = __hfma2(e4m3x2_to_h2(q1.y), h1, acck[1]);
                acck[2] = __hfma2(e4m3x2_to_h2(q1.y >> 16), h1, acck[2]);
                acck[3] = __hfma2(e4m3x2_to_h2(q1.z), h1, acck[3]);
                acck[4] = __hfma2(e4m3x2_to_h2(q1.z >> 16), h1, acck[4]);
                acck[5] = __hfma2(e4m3x2_to_h2(q1.w), h1, acck[5]);
            }
        }
        {
            const float x = accd + ACT_SHIFT;
            const float sigma = fmaxf(x, 0.0f) + log1pf(__expf(-fabsf(x)));
            g_alpha[sidx] = 1.0f - __expf(-sigma * STEPDIST);
        }

        // ---- features -> F smem (rows warp-private) ----
        {
            float feat[40];
#pragma unroll
            for (int j = 0; j < 6; j++) {
                const float2 kc = __half22float2(acck[j]);
                feat[2 * j] = kc.x;
                feat[2 * j + 1] = kc.y;
            }
            feat[12] = pvx; feat[13] = pvy; feat[14] = pvz;
            {
                const float v3[3] = {pvx, pvy, pvz};
#pragma unroll
                for (int i = 0; i < 3; i++) {
#pragma unroll
                    for (int p = 0; p < 4; p++) {
                        float sv, cv;
                        __sincosf(v3[i] * (float)(1 << p), &sv, &cv);
                        feat[15 + i * 4 + p] = sv;
                        feat[27 + i * 4 + p] = cv;
                    }
                }
            }
            feat[39] = 0.0f;
            uint32_t* F = smw + SM_F;
#pragma unroll
            for (int j = 0; j < 20; j++)
                F[tid * 28 + j] = pack_bf16x2(feat[2 * j], feat[2 * j + 1]);
#pragma unroll
            for (int j = 20; j < 24; j++) F[tid * 28 + j] = 0u;
        }
        __syncwarp();

        // ---- issue next tile's gather (flies under the MLP below) ----
        const int tcur = t;
        const int tn = t + GRID_P;
        const bool have_next = (tn < NTILES);
        if (have_next) {
            t = tn;
            issue(tn);
            CP_COMMIT();
        }

        // ---- layer 0 (bf16): C fragments -> fp8 layer-1 A fragments in registers ----
        uint32_t af[2][3][4];
#pragma unroll
        for (int tt = 0; tt < 2; tt++) {
#pragma unroll
            for (int kk = 0; kk < 3; kk++) {
                const uint32_t addr = Fb +
                    (((m0 + 16 * tt + ((amt & 1) << 3) + arow) * 28 + 8 * kk + ((amt >> 1) << 2)) << 2);
                ldsm_x4(af[tt][kk][0], af[tt][kk][1], af[tt][kk][2], af[tt][kk][3], addr);
            }
        }
        uint32_t a8[2][4][4];
#pragma unroll
        for (int nt = 0; nt < 16; nt++) {
            const int n0 = nt * 8;
            const float cb0 = sm[SM_B0 + n0 + 2 * q];
            const float cb1 = sm[SM_B0 + n0 + 2 * q + 1];
            float C0[4] = {cb0, cb1, cb0, cb1};
            float C1[4] = {cb0, cb1, cb0, cb1};
            uint32_t bb[6];
            ldsm_x4(bb[0], bb[1], bb[2], bb[3],
                    W0b + (((n0 + arow) * 28 + (amt << 2)) << 2));
            ldsm_x2(bb[4], bb[5],
                    W0b + (((n0 + arow) * 28 + 16 + ((amt & 1) << 2)) << 2));
#pragma unroll
            for (int kk = 0; kk < 3; kk++) {
                mma_bf16(C0, af[0][kk][0], af[0][kk][1], af[0][kk][2], af[0][kk][3],
                         bb[2 * kk], bb[2 * kk + 1]);
                mma_bf16(C1, af[1][kk][0], af[1][kk][1], af[1][kk][2], af[1][kk][3],
                         bb[2 * kk], bb[2 * kk + 1]);
            }
            // relu -> e4m3 pack: P = [lo(c0),lo(c1),hi(c0),hi(c1)] bytes
            const uint32_t P0 = pack_e4m3x2(fmaxf(C0[0], 0.0f), fmaxf(C0[1], 0.0f))
                              | (pack_e4m3x2(fmaxf(C0[2], 0.0f), fmaxf(C0[3], 0.0f)) << 16);
            const uint32_t P1 = pack_e4m3x2(fmaxf(C1[0], 0.0f), fmaxf(C1[1], 0.0f))
                              | (pack_e4m3x2(fmaxf(C1[2], 0.0f), fmaxf(C1[3], 0.0f)) << 16);
            // stage 1: 4-wide col groups within q-pairs
            const uint32_t R0 = __shfl_xor_sync(0xFFFFFFFFu, P0, 1);
            const uint32_t R1 = __shfl_xor_sync(0xFFFFFFFFu, P1, 1);
            const uint32_t sel_lo = (q & 1) ? 0x1054u : 0x5410u;
            const uint32_t sel_hi = (q & 1) ? 0x3276u : 0x7632u;
            const uint32_t glo0 = __byte_perm(P0, R0, sel_lo);
            const uint32_t ghi0 = __byte_perm(P0, R0, sel_hi);
            const uint32_t glo1 = __byte_perm(P1, R1, sel_lo);
            const uint32_t ghi1 = __byte_perm(P1, R1, sel_hi);
            // stage 2: route off0<->off4 between q=1 and q=2
            const uint32_t slo0 = __shfl_xor_sync(0xFFFFFFFFu, glo0, 3);
            const uint32_t shi0 = __shfl_xor_sync(0xFFFFFFFFu, ghi0, 3);
            const uint32_t slo1 = __shfl_xor_sync(0xFFFFFFFFu, glo1, 3);
            const uint32_t shi1 = __shfl_xor_sync(0xFFFFFFFFu, ghi1, 3);
            const uint32_t Hlo0 = swapq ? slo0 : glo0;
            const uint32_t Hhi0 = swapq ? shi0 : ghi0;
            const uint32_t Hlo1 = swapq ? slo1 : glo1;
            const uint32_t Hhi1 = swapq ? shi1 : ghi1;
            // capture into fp8 a-frags: nt = 4*kk + 2*j + spar
            const int kk1 = nt >> 2;
            const int jj2 = (nt >> 1) & 1;
            const bool cap = (spar_q == (nt & 1));
            a8[0][kk1][2 * jj2]     = cap ? Hlo0 : a8[0][kk1][2 * jj2];
            a8[0][kk1][2 * jj2 + 1] = cap ? Hhi0 : a8[0][kk1][2 * jj2 + 1];
            a8[1][kk1][2 * jj2]     = cap ? Hlo1 : a8[1][kk1][2 * jj2];
            a8[1][kk1][2 * jj2 + 1] = cap ? Hhi1 : a8[1][kk1][2 * jj2 + 1];
        }

        // ---- layer 1 (fp8 m16n8k32) + fused layer 2 ----
        float acc[4][3];
#pragma unroll
        for (int i = 0; i < 4; i++)
#pragma unroll
            for (int c = 0; c < 3; c++) acc[i][c] = 0.0f;

        const float* W2s = sm + SM_W2;
#pragma unroll
        for (int nt = 0; nt < 16; nt++) {
            const int n0 = nt * 8;
            const float cb0 = sm[SM_B1 + n0 + 2 * q];
            const float cb1 = sm[SM_B1 + n0 + 2 * q + 1];
            float C0[4] = {cb0, cb1, cb0, cb1};
            float C1[4] = {cb0, cb1, cb0, cb1};
#pragma unroll
            for (int kk = 0; kk < 4; kk++) {
                uint32_t b0r, b1r;
                ldsm_x2(b0r, b1r,
                        W1b8 + (((n0 + lrow) * 36 + 8 * kk + 4 * lmat) << 2));
                mma_fp8(C0, a8[0][kk][0], a8[0][kk][1], a8[0][kk][2], a8[0][kk][3], b0r, b1r);
                mma_fp8(C1, a8[1][kk][0], a8[1][kk][1], a8[1][kk][2], a8[1][kk][3], b0r, b1r);
            }
            const int col0 = n0 + 2 * q, col1 = col0 + 1;
            const float w20x = W2s[col0 * 3 + 0], w20y = W2s[col0 * 3 + 1], w20z = W2s[col0 * 3 + 2];
            const float w21x = W2s[col1 * 3 + 0], w21y = W2s[col1 * 3 + 1], w21z = W2s[col1 * 3 + 2];
            {
                const float h0 = fmaxf(C0[0], 0.0f), h1 = fmaxf(C0[1], 0.0f);
                const float h2 = fmaxf(C0[2], 0.0f), h3 = fmaxf(C0[3], 0.0f);
                acc[0][0] += h0 * w20x + h1 * w21x;
                acc[0][1] += h0 * w20y + h1 * w21y;
                acc[0][2] += h0 * w20z + h1 * w21z;
                acc[1][0] += h2 * w20x + h3 * w21x;
                acc[1][1] += h2 * w20y + h3 * w21y;
                acc[1][2] += h2 * w20z + h3 * w21z;
            }
            {
                const float h0 = fmaxf(C1[0], 0.0f), h1 = fmaxf(C1[1], 0.0f);
                const float h2 = fmaxf(C1[2], 0.0f), h3 = fmaxf(C1[3], 0.0f);
                acc[2][0] += h0 * w20x + h1 * w21x;
                acc[2][1] += h0 * w20y + h1 * w21y;
                acc[2][2] += h0 * w20z + h1 * w21z;
                acc[3][0] += h2 * w20x + h3 * w21x;
                acc[3][1] += h2 * w20y + h3 * w21y;
                acc[3][2] += h2 * w20z + h3 * w21z;
            }
        }

#pragma unroll
        for (int i = 0; i < 4; i++)
#pragma unroll
            for (int c = 0; c < 3; c++) {
                acc[i][c] += __shfl_xor_sync(0xFFFFFFFFu, acc[i][c], 1);
                acc[i][c] += __shfl_xor_sync(0xFFFFFFFFu, acc[i][c], 2);
            }

        if (q == 0) {
            const float bb0 = sm[SM_B2 + 0], bb1 = sm[SM_B2 + 1], bb2 = sm[SM_B2 + 2];
            const int rows[4] = {m0 + g8, m0 + 8 + g8, m0 + 16 + g8, m0 + 24 + g8};
#pragma unroll
            for (int i = 0; i < 4; i++) {
                const int oidx = tcur * BLOCK + rows[i];
                g_rgb0[oidx] = 1.0f / (1.0f + __expf(-(acc[i][0] + bb0)));
                g_rgb1[oidx] = 1.0f / (1.0f + __expf(-(acc[i][1] + bb1)));
                g_rgb2[oidx] = 1.0f / (1.0f + __expf(-(acc[i][2] + bb2)));
            }
        }
        __syncwarp();

        if (!have_next) break;
    }
}

// ---------------- compositing: one warp per ray ----------------
__global__ void __launch_bounds__(256)
composite_kernel(float* __restrict__ out)
{
    const int gwarp = (blockIdx.x * blockDim.x + threadIdx.x) >> 5;
    const int lane = threadIdx.x & 31;
    if (gwarp >= N_RAYS) return;
    const int r = gwarp;

    float T = 1.0f, wsum = 0.0f, a0 = 0.0f, a1 = 0.0f, a2 = 0.0f;
#pragma unroll
    for (int chunk = 0; chunk < N_SAMPLES / 32; chunk++) {
        const int off = r * N_SAMPLES + chunk * 32 + lane;
        const float alpha = g_alpha[off];
        const float c0 = g_rgb0[off];
        const float c1 = g_rgb1[off];
        const float c2 = g_rgb2[off];
        float p = 1.0f - alpha + 1e-10f;
#pragma unroll
        for (int d = 1; d < 32; d <<= 1) {
            const float up = __shfl_up_sync(0xFFFFFFFFu, p, d);
            if (lane >= d) p *= up;
        }
        float excl = __shfl_up_sync(0xFFFFFFFFu, p, 1);
        if (lane == 0) excl = 1.0f;
        const float w = alpha * T * excl;
        wsum += w;
        a0 += w * c0; a1 += w * c1; a2 += w * c2;
        T *= __shfl_sync(0xFFFFFFFFu, p, 31);
    }
#pragma unroll
    for (int d = 16; d > 0; d >>= 1) {
        wsum += __shfl_down_sync(0xFFFFFFFFu, wsum, d);
        a0 += __shfl_down_sync(0xFFFFFFFFu, a0, d);
        a1 += __shfl_down_sync(0xFFFFFFFFu, a1, d);
        a2 += __shfl_down_sync(0xFFFFFFFFu, a2, d);
    }
    if (lane == 0) {
        const float bg = 1.0f - wsum;
        out[r * 3 + 0] = a0 + bg;
        out[r * 3 + 1] = a1 + bg;
        out[r * 3 + 2] = a2 + bg;
    }
}

extern "C" void kernel_launch(void* const* d_in, const int* in_sizes, int n_in,
                              void* d_out, int out_size)
{
    const float* rays_o = (const float*)d_in[0];
    const float* rays_d = (const float*)d_in[1];
    const float* dgrid  = (const float*)d_in[2];
    const float* k0grid = (const float*)d_in[3];
    const float* w0 = (const float*)d_in[4];
    const float* b0 = (const float*)d_in[5];
    const float* w1 = (const float*)d_in[6];
    const float* b1 = (const float*)d_in[7];
    const float* w2 = (const float*)d_in[8];
    const float* b2 = (const float*)d_in[9];
    float* out = (float*)d_out;

    cudaFuncSetAttribute(point_kernel,
                         cudaFuncAttributeMaxDynamicSharedMemorySize, SMEM_BYTES);

    pack_grid_kernel<<<(GRID_D3 + 255) / 256, 256>>>(dgrid, k0grid, w0, w1);
    point_kernel<<<GRID_P, BLOCK, SMEM_BYTES>>>(rays_o, rays_d, w2, b0, b1, b2);
    composite_kernel<<<(N_RAYS * 32 + 255) / 256, 256>>>(out);
}

// round 15
// speedup vs baseline: 1.0778x; 1.0778x over previous
#include <cuda_runtime.h>
#include <cuda_fp16.h>
#include <cstdint>
#include <math.h>

#define N_RAYS 4096
#define N_SAMPLES 192
#define GRID_D 160
#define GRID_D2 (160*160)
#define GRID_D3 (160*160*160)
#define K0_DIM 12
#define XYZ_MIN (-1.2f)
#define COORD_SCALE (159.0f / 2.4f)
#define ACT_SHIFT (-4.595119850134589f)
#define STEPDIST (2.8f / 192.0f)
#define NEARV 0.2f
#define FARV 3.0f

#define NPTS (N_RAYS * N_SAMPLES)
#define BLOCK 256
#define NTILES (NPTS / BLOCK)      /* 3072 */
#define GRID_P 296                 /* 2 CTAs x 148 SMs persistent */

// ---------------- scratch ----------------
__device__ float g_alpha[NPTS];
__device__ float g_rgb0[NPTS];
__device__ float g_rgb1[NPTS];
__device__ float g_rgb2[NPTS];
__device__ uint32_t PW0T[128 * 12];    // [n][kpair] bf16x2: words 0-5 = k0 weights, 6-11 = 0
__device__ uint32_t PW1T[128 * 68];    // [n][kpair] bf16x2, k<128 real
__device__ float HB[N_RAYS * 128];     // per-ray: b0 + W0_vd @ vd_emb  (2 MB)
// packed voxel: 16B = [density bf16 | k0[0..11] e4m3 | pad16]
__device__ uint4 PG[GRID_D3];          // 65.5 MB (L2-resident)

// ---------------- smem layout (4-byte word units) ----------------
#define SM_W0T  0                      /* 128*12 = 1536 */
#define SM_W1T  1536                   /* 128*68 = 8704 */
#define SM_F    10240                  /* 256*12 = 3072 */
#define SM_W2   13312                  /* 384 */
#define SM_B1   13696                  /* 128 */
#define SM_B2   13824                  /* 4 */
#define SM_G    13828                  /* 8 x 256 x uint4 = 8192 words; byte 55312 %16==0 */
#define SM_WORDS (SM_G + 8192)
#define SMEM_BYTES (SM_WORDS * 4)      /* ~86 KB -> 2 CTAs/SM */

__device__ __forceinline__ uint32_t pack_bf16x2(float lo, float hi) {
    uint32_t u;
    asm("cvt.rn.bf16x2.f32 %0, %1, %2;" : "=r"(u) : "f"(hi), "f"(lo));
    return u;
}
__device__ __forceinline__ float bflo(uint32_t u) { return __uint_as_float(u << 16); }

__device__ __forceinline__ uint32_t pack_e4m3x2(float lo, float hi) {
    uint16_t r;
    asm("cvt.rn.satfinite.e4m3x2.f32 %0, %1, %2;" : "=h"(r) : "f"(hi), "f"(lo));
    return (uint32_t)r;
}
__device__ __forceinline__ __half2 e4m3x2_to_h2(uint32_t u) {
    uint32_t h2;
    asm("cvt.rn.f16x2.e4m3x2 %0, %1;" : "=r"(h2) : "h"((uint16_t)(u)));
    return *reinterpret_cast<__half2*>(&h2);
}

__device__ __forceinline__ uint32_t smem_u32(const void* p) {
    uint32_t a;
    asm("{ .reg .u64 t; cvta.to.shared.u64 t, %1; cvt.u32.u64 %0, t; }" : "=r"(a) : "l"(p));
    return a;
}
__device__ __forceinline__ void ldsm_x4(uint32_t& r0, uint32_t& r1, uint32_t& r2, uint32_t& r3,
                                        uint32_t addr) {
    asm volatile("ldmatrix.sync.aligned.m8n8.x4.shared.b16 {%0,%1,%2,%3}, [%4];"
                 : "=r"(r0), "=r"(r1), "=r"(r2), "=r"(r3) : "r"(addr));
}
__device__ __forceinline__ void ldsm_x2(uint32_t& r0, uint32_t& r1, uint32_t addr) {
    asm volatile("ldmatrix.sync.aligned.m8n8.x2.shared.b16 {%0,%1}, [%2];"
                 : "=r"(r0), "=r"(r1) : "r"(addr));
}
__device__ __forceinline__ void mma_bf16(float c[4],
                                         uint32_t a0, uint32_t a1, uint32_t a2, uint32_t a3,
                                         uint32_t b0, uint32_t b1) {
    asm volatile("mma.sync.aligned.m16n8k16.row.col.f32.bf16.bf16.f32 "
                 "{%0,%1,%2,%3}, {%4,%5,%6,%7}, {%8,%9}, {%0,%1,%2,%3};"
                 : "+f"(c[0]), "+f"(c[1]), "+f"(c[2]), "+f"(c[3])
                 : "r"(a0), "r"(a1), "r"(a2), "r"(a3), "r"(b0), "r"(b1));
}
#define CP_ASYNC16(dst, src) \
    asm volatile("cp.async.cg.shared.global [%0], [%1], 16;" :: "r"(dst), "l"(src))
#define CP_COMMIT() asm volatile("cp.async.commit_group;" ::: "memory")
#define CP_WAIT0()  asm volatile("cp.async.wait_group 0;" ::: "memory")

// ---------------- pack grids (+ weight prep folded in) ----------------
__global__ void __launch_bounds__(256)
pack_grid_kernel(const float* __restrict__ dgrid, const float* __restrict__ k0grid,
                 const float* __restrict__ w0, const float* __restrict__ w1)
{
    const int gid = blockIdx.x * blockDim.x + threadIdx.x;
    if (gid < 128 * 12) {
        const int n = gid / 12, wd = gid - n * 12;
        const int k = 2 * wd;
        const float lo = (k < 12) ? w0[k * 128 + n] : 0.0f;
        const float hi = (k + 1 < 12) ? w0[(k + 1) * 128 + n] : 0.0f;
        PW0T[gid] = pack_bf16x2(lo, hi);
    } else if (gid < 128 * 12 + 128 * 68) {
        const int i = gid - 128 * 12;
        const int n = i / 68, wd = i - n * 68;
        const int k = 2 * wd;
        const float lo = (k < 128) ? w1[k * 128 + n] : 0.0f;
        const float hi = (k + 1 < 128) ? w1[(k + 1) * 128 + n] : 0.0f;
        PW1T[i] = pack_bf16x2(lo, hi);
    }
    const int v = gid;
    if (v >= GRID_D3) return;
    const float d = dgrid[v];
    float k[12];
#pragma unroll
    for (int c = 0; c < K0_DIM; c++) k[c] = k0grid[c * GRID_D3 + v];
    const uint32_t dbf = pack_bf16x2(d, 0.0f) & 0xffffu;
    const uint32_t a = dbf | (pack_e4m3x2(k[0], k[1]) << 16);
    const uint32_t b = pack_e4m3x2(k[2], k[3]) | (pack_e4m3x2(k[4], k[5]) << 16);
    const uint32_t c = pack_e4m3x2(k[6], k[7]) | (pack_e4m3x2(k[8], k[9]) << 16);
    const uint32_t e = pack_e4m3x2(k[10], k[11]);
    PG[v] = make_uint4(a, b, c, e);
}

// ---------------- per-ray hidden bias: hb = b0 + W0_vd @ vd_emb ----------------
__global__ void __launch_bounds__(128)
hb_kernel(const float* __restrict__ rays_d, const float* __restrict__ w0,
          const float* __restrict__ b0)
{
    const int r = blockIdx.x;
    const int n = threadIdx.x;
    const float dx = rays_d[r * 3 + 0], dy = rays_d[r * 3 + 1], dz = rays_d[r * 3 + 2];
    const float inv = rsqrtf(dx * dx + dy * dy + dz * dz);
    const float vx = dx * inv, vy = dy * inv, vz = dz * inv;
    float vd[27];
    vd[0] = vx; vd[1] = vy; vd[2] = vz;
    const float v3[3] = {vx, vy, vz};
#pragma unroll
    for (int i = 0; i < 3; i++) {
#pragma unroll
        for (int p = 0; p < 4; p++) {
            float sv, cv;
            __sincosf(v3[i] * (float)(1 << p), &sv, &cv);
            vd[3 + i * 4 + p] = sv;
            vd[15 + i * 4 + p] = cv;
        }
    }
    float acc = b0[n];
#pragma unroll
    for (int k = 0; k < 27; k++) acc += vd[k] * w0[(12 + k) * 128 + n];
    HB[r * 128 + n] = acc;
}

// ---------------- persistent point kernel ----------------
__global__ void __launch_bounds__(BLOCK, 2)
point_kernel(const float* __restrict__ rays_o,
             const float* __restrict__ rays_d,
             const float* __restrict__ w2,
             const float* __restrict__ b1,
             const float* __restrict__ b2)
{
    extern __shared__ float sm[];
    uint32_t* smw = (uint32_t*)sm;
    const int tid = threadIdx.x;
    const uint32_t sm_base = smem_u32(sm);
    const uint32_t gdst0 = sm_base + SM_G * 4 + (uint32_t)tid * 16;

    // ---- stage static weights ONCE per CTA ----
    {
        float4* d0 = (float4*)(smw + SM_W0T);
        const float4* s0 = (const float4*)PW0T;
        for (int i = tid; i < 384; i += BLOCK) d0[i] = s0[i];
        float4* d1 = (float4*)(smw + SM_W1T);
        const float4* s1 = (const float4*)PW1T;
        for (int i = tid; i < 2176; i += BLOCK) d1[i] = s1[i];
    }
    for (int i = tid; i < 384; i += BLOCK) sm[SM_W2 + i] = w2[i];
    if (tid < 128) sm[SM_B1 + tid] = b1[tid];
    if (tid < 3) sm[SM_B2 + tid] = b2[tid];

    const int lane = tid & 31;
    const int warp = tid >> 5;
    const int g8 = lane >> 2;
    const int q = lane & 3;
    const int m0 = warp * 32;
    const int arow = lane & 7;
    const int amt = lane >> 3;
    const int lrow = lane & 7;
    const int lmat = (lane >> 3) & 1;
    const uint32_t Fb  = sm_base + SM_F * 4;
    const uint32_t W0b = sm_base + SM_W0T * 4;
    const uint32_t W1b = sm_base + SM_W1T * 4;
    const uint4* gbuf = (const uint4*)(smw + SM_G);

    float wxy0, wxy1, wxy2, wxy3, ezr, fzr;
    int sidx, iloc;
    int t = blockIdx.x;

    auto issue = [&](int tt) {
        const int idx = tt * BLOCK + tid;
        const int r = idx / N_SAMPLES;
        const int s = idx - r * N_SAMPLES;
        iloc = r - (tt * BLOCK) / N_SAMPLES;   // 0..2 within tile
        float dx = rays_d[r * 3 + 0], dy = rays_d[r * 3 + 1], dz = rays_d[r * 3 + 2];
        const float inv = rsqrtf(dx * dx + dy * dy + dz * dz);
        const float vx = dx * inv, vy = dy * inv, vz = dz * inv;
        const float tval = NEARV + (FARV - NEARV) * ((float)s + 0.5f) / (float)N_SAMPLES;
        float px = rays_o[r * 3 + 0] + vx * tval;
        float py = rays_o[r * 3 + 1] + vy * tval;
        float pz = rays_o[r * 3 + 2] + vz * tval;
        const float nrm = fmaxf(fabsf(px), fmaxf(fabsf(py), fabsf(pz)));
        if (nrm > 1.0f) {
            const float invn = 1.0f / nrm;
            const float sc = (1.2f - 0.2f * invn) * invn;
            px *= sc; py *= sc; pz *= sc;
        }
        float gx = (px - XYZ_MIN) * COORD_SCALE;
        float gy = (py - XYZ_MIN) * COORD_SCALE;
        float gz = (pz - XYZ_MIN) * COORD_SCALE;
        gx = fminf(fmaxf(gx, 0.0f), 159.0f);
        gy = fminf(fmaxf(gy, 0.0f), 159.0f);
        gz = fminf(fmaxf(gz, 0.0f), 159.0f);
        const int ix = min((int)floorf(gx), 158);
        const int iy = min((int)floorf(gy), 158);
        const int iz = min((int)floorf(gz), 158);
        const float fx = gx - (float)ix, fy = gy - (float)iy, fz = gz - (float)iz;
        const float ex = 1.0f - fx, ey = 1.0f - fy;
        const int base = ix * GRID_D2 + iy * GRID_D + iz;
        wxy0 = ex * ey; wxy1 = ex * fy; wxy2 = fx * ey; wxy3 = fx * fy;
        ezr = 1.0f - fz; fzr = fz;
        sidx = idx;
        const int vb[4] = {base, base + GRID_D, base + GRID_D2, base + GRID_D2 + GRID_D};
#pragma unroll
        for (int p = 0; p < 4; p++) {
            const char* src = (const char*)(PG + vb[p]);
            CP_ASYNC16(gdst0 + (uint32_t)(2 * p) * 4096u, src);
            CP_ASYNC16(gdst0 + (uint32_t)(2 * p + 1) * 4096u, src + 16);
        }
    };

    issue(t);
    CP_COMMIT();
    __syncthreads();

    while (true) {
        // ---- dynamic B rows: hb vectors of this tile's (up to) 3 rays ----
        {
            const int rb = (t * BLOCK) / N_SAMPLES;
            if (tid < 128) {
                const int n = tid;
                const float h0 = HB[min(rb, N_RAYS - 1) * 128 + n];
                const float h1 = HB[min(rb + 1, N_RAYS - 1) * 128 + n];
                smw[SM_W0T + n * 12 + 6] = pack_bf16x2(h0, h1);
            } else {
                const int n = tid - 128;
                const float h2 = HB[min(rb + 2, N_RAYS - 1) * 128 + n];
                smw[SM_W0T + n * 12 + 7] = pack_bf16x2(h2, 0.0f);
            }
        }

        CP_WAIT0();

        // ---- decode gather buffer -> density + k0 features ----
        float accd = 0.0f;
        __half2 acck[6];
#pragma unroll
        for (int j = 0; j < 6; j++) acck[j] = __float2half2_rn(0.0f);
        {
            const float wxy[4] = {wxy0, wxy1, wxy2, wxy3};
#pragma unroll
            for (int p = 0; p < 4; p++) {
                const uint4 q0 = gbuf[(2 * p) * 256 + tid];
                const uint4 q1 = gbuf[(2 * p + 1) * 256 + tid];
                const float wz0 = wxy[p] * ezr, wz1 = wxy[p] * fzr;
                accd += bflo(q0.x) * wz0 + bflo(q1.x) * wz1;
                const __half2 h0 = __float2half2_rn(wz0);
                const __half2 h1 = __float2half2_rn(wz1);
                acck[0] = __hfma2(e4m3x2_to_h2(q0.x >> 16), h0, acck[0]);
                acck[1] = __hfma2(e4m3x2_to_h2(q0.y), h0, acck[1]);
                acck[2] = __hfma2(e4m3x2_to_h2(q0.y >> 16), h0, acck[2]);
                acck[3] = __hfma2(e4m3x2_to_h2(q0.z), h0, acck[3]);
                acck[4] = __hfma2(e4m3x2_to_h2(q0.z >> 16), h0, acck[4]);
                acck[5] = __hfma2(e4m3x2_to_h2(q0.w), h0, acck[5]);
                acck[0] = __hfma2(e4m3x2_to_h2(q1.x >> 16), h1, acck[0]);
                acck[1] = __hfma2(e4m3x2_to_h2(q1.y), h1, acck[1]);
                acck[2] = __hfma2(e4m3x2_to_h2(q1.y >> 16), h1, acck[2]);
                acck[3] = __hfma2(e4m3x2_to_h2(q1.z), h1, acck[3]);
                acck[4] = __hfma2(e4m3x2_to_h2(q1.z >> 16), h1, acck[4]);
                acck[5] = __hfma2(e4m3x2_to_h2(q1.w), h1, acck[5]);
            }
        }
        {
            const float x = accd + ACT_SHIFT;
            const float sigma = fmaxf(x, 0.0f) + log1pf(__expf(-fabsf(x)));
            g_alpha[sidx] = 1.0f - __expf(-sigma * STEPDIST);
        }

        // ---- features -> F smem: 12 k0 + 3 ray indicators + pad (K=16) ----
        {
            uint32_t* F = smw + SM_F;
#pragma unroll
            for (int j = 0; j < 6; j++) {
                const float2 kc = __half22float2(acck[j]);
                F[tid * 12 + j] = pack_bf16x2(kc.x, kc.y);
            }
            F[tid * 12 + 6] = pack_bf16x2(iloc == 0 ? 1.0f : 0.0f, iloc == 1 ? 1.0f : 0.0f);
            F[tid * 12 + 7] = pack_bf16x2(iloc == 2 ? 1.0f : 0.0f, 0.0f);
        }

        __syncthreads();   // F + dynamic B words visible to all warps

        // ---- issue next tile's gather (flies under the MLP below) ----
        const int tcur = t;
        const int tn = t + GRID_P;
        const bool have_next = (tn < NTILES);
        if (have_next) {
            t = tn;
            issue(tn);
            CP_COMMIT();
        }

        // ---- layer 0 (K=16, one k-step): C -> layer-1 A fragments in registers ----
        uint32_t af[2][4];
#pragma unroll
        for (int tt = 0; tt < 2; tt++) {
            const uint32_t addr = Fb +
                (((m0 + 16 * tt + ((amt & 1) << 3) + arow) * 12 + ((amt >> 1) << 2)) << 2);
            ldsm_x4(af[tt][0], af[tt][1], af[tt][2], af[tt][3], addr);
        }
        uint32_t a1f[2][8][4];
#pragma unroll
        for (int nt = 0; nt < 16; nt++) {
            const int n0 = nt * 8;
            float C0[4] = {0.0f, 0.0f, 0.0f, 0.0f};
            float C1[4] = {0.0f, 0.0f, 0.0f, 0.0f};
            uint32_t b0r, b1r;
            ldsm_x2(b0r, b1r, W0b + (((n0 + lrow) * 12 + 4 * lmat) << 2));
            mma_bf16(C0, af[0][0], af[0][1], af[0][2], af[0][3], b0r, b1r);
            mma_bf16(C1, af[1][0], af[1][1], af[1][2], af[1][3], b0r, b1r);
            const int kk1 = nt >> 1;
            const int hi = (nt & 1) << 1;
            a1f[0][kk1][hi]     = pack_bf16x2(fmaxf(C0[0], 0.0f), fmaxf(C0[1], 0.0f));
            a1f[0][kk1][hi + 1] = pack_bf16x2(fmaxf(C0[2], 0.0f), fmaxf(C0[3], 0.0f));
            a1f[1][kk1][hi]     = pack_bf16x2(fmaxf(C1[0], 0.0f), fmaxf(C1[1], 0.0f));
            a1f[1][kk1][hi + 1] = pack_bf16x2(fmaxf(C1[2], 0.0f), fmaxf(C1[3], 0.0f));
        }

        // ---- layer 1 + fused layer 2 ----
        float acc[4][3];
#pragma unroll
        for (int i = 0; i < 4; i++)
#pragma unroll
            for (int c = 0; c < 3; c++) acc[i][c] = 0.0f;

        const float* W2s = sm + SM_W2;
#pragma unroll
        for (int nt = 0; nt < 16; nt++) {
            const int n0 = nt * 8;
            const float cb0 = sm[SM_B1 + n0 + 2 * q];
            const float cb1 = sm[SM_B1 + n0 + 2 * q + 1];
            float C0[4] = {cb0, cb1, cb0, cb1};
            float C1[4] = {cb0, cb1, cb0, cb1};
#pragma unroll
            for (int kp = 0; kp < 4; kp++) {
                uint32_t w0r, w1r, w2r, w3r;
                ldsm_x4(w0r, w1r, w2r, w3r,
                        W1b + (((n0 + arow) * 68 + 16 * kp + (amt << 2)) << 2));
                const int kk = 2 * kp;
                mma_bf16(C0, a1f[0][kk][0], a1f[0][kk][1], a1f[0][kk][2], a1f[0][kk][3], w0r, w1r);
                mma_bf16(C1, a1f[1][kk][0], a1f[1][kk][1], a1f[1][kk][2], a1f[1][kk][3], w0r, w1r);
                mma_bf16(C0, a1f[0][kk + 1][0], a1f[0][kk + 1][1], a1f[0][kk + 1][2], a1f[0][kk + 1][3], w2r, w3r);
                mma_bf16(C1, a1f[1][kk + 1][0], a1f[1][kk + 1][1], a1f[1][kk + 1][2], a1f[1][kk + 1][3], w2r, w3r);
            }
            const int col0 = n0 + 2 * q, col1 = col0 + 1;
            const float w20x = W2s[col0 * 3 + 0], w20y = W2s[col0 * 3 + 1], w20z = W2s[col0 * 3 + 2];
            const float w21x = W2s[col1 * 3 + 0], w21y = W2s[col1 * 3 + 1], w21z = W2s[col1 * 3 + 2];
            {
                const float h0 = fmaxf(C0[0], 0.0f), h1 = fmaxf(C0[1], 0.0f);
                const float h2 = fmaxf(C0[2], 0.0f), h3 = fmaxf(C0[3], 0.0f);
                acc[0][0] += h0 * w20x + h1 * w21x;
                acc[0][1] += h0 * w20y + h1 * w21y;
                acc[0][2] += h0 * w20z + h1 * w21z;
                acc[1][0] += h2 * w20x + h3 * w21x;
                acc[1][1] += h2 * w20y + h3 * w21y;
                acc[1][2] += h2 * w20z + h3 * w21z;
            }
            {
                const float h0 = fmaxf(C1[0], 0.0f), h1 = fmaxf(C1[1], 0.0f);
                const float h2 = fmaxf(C1[2], 0.0f), h3 = fmaxf(C1[3], 0.0f);
                acc[2][0] += h0 * w20x + h1 * w21x;
                acc[2][1] += h0 * w20y + h1 * w21y;
                acc[2][2] += h0 * w20z + h1 * w21z;
                acc[3][0] += h2 * w20x + h3 * w21x;
                acc[3][1] += h2 * w20y + h3 * w21y;
                acc[3][2] += h2 * w20z + h3 * w21z;
            }
        }

#pragma unroll
        for (int i = 0; i < 4; i++)
#pragma unroll
            for (int c = 0; c < 3; c++) {
                acc[i][c] += __shfl_xor_sync(0xFFFFFFFFu, acc[i][c], 1);
                acc[i][c] += __shfl_xor_sync(0xFFFFFFFFu, acc[i][c], 2);
            }

        if (q == 0) {
            const float bb0 = sm[SM_B2 + 0], bb1 = sm[SM_B2 + 1], bb2 = sm[SM_B2 + 2];
            const int rows[4] = {m0 + g8, m0 + 8 + g8, m0 + 16 + g8, m0 + 24 + g8};
#pragma unroll
            for (int i = 0; i < 4; i++) {
                const int oidx = tcur * BLOCK + rows[i];
                g_rgb0[oidx] = 1.0f / (1.0f + __expf(-(acc[i][0] + bb0)));
                g_rgb1[oidx] = 1.0f / (1.0f + __expf(-(acc[i][1] + bb1)));
                g_rgb2[oidx] = 1.0f / (1.0f + __expf(-(acc[i][2] + bb2)));
            }
        }

        __syncthreads();   // all warps done with F + dynamic B before next overwrite

        if (!have_next) break;
    }
}

// ---------------- compositing: one warp per ray ----------------
__global__ void __launch_bounds__(256)
composite_kernel(float* __restrict__ out)
{
    const int gwarp = (blockIdx.x * blockDim.x + threadIdx.x) >> 5;
    const int lane = threadIdx.x & 31;
    if (gwarp >= N_RAYS) return;
    const int r = gwarp;

    float T = 1.0f, wsum = 0.0f, a0 = 0.0f, a1 = 0.0f, a2 = 0.0f;
#pragma unroll
    for (int chunk = 0; chunk < N_SAMPLES / 32; chunk++) {
        const int off = r * N_SAMPLES + chunk * 32 + lane;
        const float alpha = g_alpha[off];
        const float c0 = g_rgb0[off];
        const float c1 = g_rgb1[off];
        const float c2 = g_rgb2[off];
        float p = 1.0f - alpha + 1e-10f;
#pragma unroll
        for (int d = 1; d < 32; d <<= 1) {
            const float up = __shfl_up_sync(0xFFFFFFFFu, p, d);
            if (lane >= d) p *= up;
        }
        float excl = __shfl_up_sync(0xFFFFFFFFu, p, 1);
        if (lane == 0) excl = 1.0f;
        const float w = alpha * T * excl;
        wsum += w;
        a0 += w * c0; a1 += w * c1; a2 += w * c2;
        T *= __shfl_sync(0xFFFFFFFFu, p, 31);
    }
#pragma unroll
    for (int d = 16; d > 0; d >>= 1) {
        wsum += __shfl_down_sync(0xFFFFFFFFu, wsum, d);
        a0 += __shfl_down_sync(0xFFFFFFFFu, a0, d);
        a1 += __shfl_down_sync(0xFFFFFFFFu, a1, d);
        a2 += __shfl_down_sync(0xFFFFFFFFu, a2, d);
    }
    if (lane == 0) {
        const float bg = 1.0f - wsum;
        out[r * 3 + 0] = a0 + bg;
        out[r * 3 + 1] = a1 + bg;
        out[r * 3 + 2] = a2 + bg;
    }
}

extern "C" void kernel_launch(void* const* d_in, const int* in_sizes, int n_in,
                              void* d_out, int out_size)
{
    const float* rays_o = (const float*)d_in[0];
    const float* rays_d = (const float*)d_in[1];
    const float* dgrid  = (const float*)d_in[2];
    const float* k0grid = (const float*)d_in[3];
    const float* w0 = (const float*)d_in[4];
    const float* b0 = (const float*)d_in[5];
    const float* w1 = (const float*)d_in[6];
    const float* b1 = (const float*)d_in[7];
    const float* w2 = (const float*)d_in[8];
    const float* b2 = (const float*)d_in[9];
    float* out = (float*)d_out;

    cudaFuncSetAttribute(point_kernel,
                         cudaFuncAttributeMaxDynamicSharedMemorySize, SMEM_BYTES);

    pack_grid_kernel<<<(GRID_D3 + 255) / 256, 256>>>(dgrid, k0grid, w0, w1);
    hb_kernel<<<N_RAYS, 128>>>(rays_d, w0, b0);
    point_kernel<<<GRID_P, BLOCK, SMEM_BYTES>>>(rays_o, rays_d, w2, b1, b2);
    composite_kernel<<<(N_RAYS * 32 + 255) / 256, 256>>>(out);
}

// round 16
// speedup vs baseline: 1.1137x; 1.0333x over previous
#include <cuda_runtime.h>
#include <cuda_fp16.h>
#include <cstdint>
#include <math.h>

#define N_RAYS 4096
#define N_SAMPLES 192
#define GRID_D 160
#define GRID_D2 (160*160)
#define GRID_D3 (160*160*160)
#define K0_DIM 12
#define XYZ_MIN (-1.2f)
#define COORD_SCALE (159.0f / 2.4f)
#define ACT_SHIFT (-4.595119850134589f)
#define STEPDIST (2.8f / 192.0f)
#define NEARV 0.2f
#define FARV 3.0f

#define BLOCK 192                  /* one ray per tile */
#define NTILES N_RAYS              /* 4096 */
#define GRID_P 296                 /* 2 CTAs x 148 SMs persistent */

// ---------------- scratch ----------------
__device__ uint32_t PW0T[128 * 12];    // [n][kpair] bf16x2: words 0-5 = k0 weights, 6-11 = 0
__device__ uint32_t PW1T[128 * 68];    // [n][kpair] bf16x2, k<128 real
__device__ float HB[N_RAYS * 128];     // per-ray: b0 + W0_vd @ vd_emb  (2 MB)
// packed voxel: 16B = [density bf16 | k0[0..11] e4m3 | pad16]
__device__ uint4 PG[GRID_D3];          // 65.5 MB (L2-resident)

// ---------------- smem layout (4-byte word units) ----------------
#define SM_W0T  0                      /* 1536 */
#define SM_W1T  1536                   /* 8704 */
#define SM_F    10240                  /* 192*12 = 2304 */
#define SM_W2   12544                  /* 384 */
#define SM_B1   12928                  /* 128 */
#define SM_B2   13056                  /* 4 */
#define SM_HB   13060                  /* 128 */
#define SM_RGB0 13188                  /* 192 */
#define SM_RGB1 13380                  /* 192 */
#define SM_RGB2 13572                  /* 192 */
#define SM_PART 13764                  /* 6*8 = 48 */
#define SM_G    13812                  /* 8 x 192 x uint4 = 6144 words; byte 55248 %16==0 */
#define SM_WORDS (SM_G + 6144)
#define SMEM_BYTES (SM_WORDS * 4)      /* ~78 KB -> 2 CTAs/SM */

__device__ __forceinline__ uint32_t pack_bf16x2(float lo, float hi) {
    uint32_t u;
    asm("cvt.rn.bf16x2.f32 %0, %1, %2;" : "=r"(u) : "f"(hi), "f"(lo));
    return u;
}
__device__ __forceinline__ float bflo(uint32_t u) { return __uint_as_float(u << 16); }

__device__ __forceinline__ uint32_t pack_e4m3x2(float lo, float hi) {
    uint16_t r;
    asm("cvt.rn.satfinite.e4m3x2.f32 %0, %1, %2;" : "=h"(r) : "f"(hi), "f"(lo));
    return (uint32_t)r;
}
__device__ __forceinline__ __half2 e4m3x2_to_h2(uint32_t u) {
    uint32_t h2;
    asm("cvt.rn.f16x2.e4m3x2 %0, %1;" : "=r"(h2) : "h"((uint16_t)(u)));
    return *reinterpret_cast<__half2*>(&h2);
}

__device__ __forceinline__ uint32_t smem_u32(const void* p) {
    uint32_t a;
    asm("{ .reg .u64 t; cvta.to.shared.u64 t, %1; cvt.u32.u64 %0, t; }" : "=r"(a) : "l"(p));
    return a;
}
__device__ __forceinline__ void ldsm_x4(uint32_t& r0, uint32_t& r1, uint32_t& r2, uint32_t& r3,
                                        uint32_t addr) {
    asm volatile("ldmatrix.sync.aligned.m8n8.x4.shared.b16 {%0,%1,%2,%3}, [%4];"
                 : "=r"(r0), "=r"(r1), "=r"(r2), "=r"(r3) : "r"(addr));
}
__device__ __forceinline__ void ldsm_x2(uint32_t& r0, uint32_t& r1, uint32_t addr) {
    asm volatile("ldmatrix.sync.aligned.m8n8.x2.shared.b16 {%0,%1}, [%2];"
                 : "=r"(r0), "=r"(r1) : "r"(addr));
}
__device__ __forceinline__ void mma_bf16(float c[4],
                                         uint32_t a0, uint32_t a1, uint32_t a2, uint32_t a3,
                                         uint32_t b0, uint32_t b1) {
    asm volatile("mma.sync.aligned.m16n8k16.row.col.f32.bf16.bf16.f32 "
                 "{%0,%1,%2,%3}, {%4,%5,%6,%7}, {%8,%9}, {%0,%1,%2,%3};"
                 : "+f"(c[0]), "+f"(c[1]), "+f"(c[2]), "+f"(c[3])
                 : "r"(a0), "r"(a1), "r"(a2), "r"(a3), "r"(b0), "r"(b1));
}
#define CP_ASYNC16(dst, src) \
    asm volatile("cp.async.cg.shared.global [%0], [%1], 16;" :: "r"(dst), "l"(src))
#define CP_COMMIT() asm volatile("cp.async.commit_group;" ::: "memory")
#define CP_WAIT0()  asm volatile("cp.async.wait_group 0;" ::: "memory")

// ---------------- pack grids (+ weight prep folded in) ----------------
__global__ void __launch_bounds__(256)
pack_grid_kernel(const float* __restrict__ dgrid, const float* __restrict__ k0grid,
                 const float* __restrict__ w0, const float* __restrict__ w1)
{
    const int gid = blockIdx.x * blockDim.x + threadIdx.x;
    if (gid < 128 * 12) {
        const int n = gid / 12, wd = gid - n * 12;
        const int k = 2 * wd;
        const float lo = (k < 12) ? w0[k * 128 + n] : 0.0f;
        const float hi = (k + 1 < 12) ? w0[(k + 1) * 128 + n] : 0.0f;
        PW0T[gid] = pack_bf16x2(lo, hi);
    } else if (gid < 128 * 12 + 128 * 68) {
        const int i = gid - 128 * 12;
        const int n = i / 68, wd = i - n * 68;
        const int k = 2 * wd;
        const float lo = (k < 128) ? w1[k * 128 + n] : 0.0f;
        const float hi = (k + 1 < 128) ? w1[(k + 1) * 128 + n] : 0.0f;
        PW1T[i] = pack_bf16x2(lo, hi);
    }
    const int v = gid;
    if (v >= GRID_D3) return;
    const float d = dgrid[v];
    float k[12];
#pragma unroll
    for (int c = 0; c < K0_DIM; c++) k[c] = k0grid[c * GRID_D3 + v];
    const uint32_t dbf = pack_bf16x2(d, 0.0f) & 0xffffu;
    const uint32_t a = dbf | (pack_e4m3x2(k[0], k[1]) << 16);
    const uint32_t b = pack_e4m3x2(k[2], k[3]) | (pack_e4m3x2(k[4], k[5]) << 16);
    const uint32_t c = pack_e4m3x2(k[6], k[7]) | (pack_e4m3x2(k[8], k[9]) << 16);
    const uint32_t e = pack_e4m3x2(k[10], k[11]);
    PG[v] = make_uint4(a, b, c, e);
}

// ---------------- per-ray hidden bias: hb = b0 + W0_vd @ vd_emb ----------------
__global__ void __launch_bounds__(128)
hb_kernel(const float* __restrict__ rays_d, const float* __restrict__ w0,
          const float* __restrict__ b0)
{
    const int r = blockIdx.x;
    const int n = threadIdx.x;
    const float dx = rays_d[r * 3 + 0], dy = rays_d[r * 3 + 1], dz = rays_d[r * 3 + 2];
    const float inv = rsqrtf(dx * dx + dy * dy + dz * dz);
    const float vx = dx * inv, vy = dy * inv, vz = dz * inv;
    float vd[27];
    vd[0] = vx; vd[1] = vy; vd[2] = vz;
    const float v3[3] = {vx, vy, vz};
#pragma unroll
    for (int i = 0; i < 3; i++) {
#pragma unroll
        for (int p = 0; p < 4; p++) {
            float sv, cv;
            __sincosf(v3[i] * (float)(1 << p), &sv, &cv);
            vd[3 + i * 4 + p] = sv;
            vd[15 + i * 4 + p] = cv;
        }
    }
    float acc = b0[n];
#pragma unroll
    for (int k = 0; k < 27; k++) acc += vd[k] * w0[(12 + k) * 128 + n];
    HB[r * 128 + n] = acc;
}

// ---------------- persistent point+composite kernel: 1 ray / tile ----------------
__global__ void __launch_bounds__(BLOCK, 2)
point_kernel(const float* __restrict__ rays_o,
             const float* __restrict__ rays_d,
             const float* __restrict__ w2,
             const float* __restrict__ b1,
             const float* __restrict__ b2,
             float* __restrict__ out)
{
    extern __shared__ float sm[];
    uint32_t* smw = (uint32_t*)sm;
    const int tid = threadIdx.x;
    const uint32_t sm_base = smem_u32(sm);
    const uint32_t gdst0 = sm_base + SM_G * 4 + (uint32_t)tid * 16;

    // ---- stage static weights ONCE per CTA ----
    {
        float4* d0 = (float4*)(smw + SM_W0T);
        const float4* s0 = (const float4*)PW0T;
        for (int i = tid; i < 384; i += BLOCK) d0[i] = s0[i];
        float4* d1 = (float4*)(smw + SM_W1T);
        const float4* s1 = (const float4*)PW1T;
        for (int i = tid; i < 2176; i += BLOCK) d1[i] = s1[i];
    }
    for (int i = tid; i < 384; i += BLOCK) sm[SM_W2 + i] = w2[i];
    if (tid < 128) sm[SM_B1 + tid] = b1[tid];
    if (tid < 3) sm[SM_B2 + tid] = b2[tid];

    const int lane = tid & 31;
    const int warp = tid >> 5;                 // 0..5
    const int g8 = lane >> 2;
    const int q = lane & 3;
    const int m0 = warp * 32;
    const int arow = lane & 7;
    const int amt = lane >> 3;
    const int lrow = lane & 7;
    const int lmat = (lane >> 3) & 1;
    const uint32_t Fb  = sm_base + SM_F * 4;
    const uint32_t W0b = sm_base + SM_W0T * 4;
    const uint32_t W1b = sm_base + SM_W1T * 4;
    const uint4* gbuf = (const uint4*)(smw + SM_G);

    float wxy0, wxy1, wxy2, wxy3, ezr, fzr;
    int t = blockIdx.x;

    auto issue = [&](int ray) {
        const int s = tid;
        float dx = rays_d[ray * 3 + 0], dy = rays_d[ray * 3 + 1], dz = rays_d[ray * 3 + 2];
        const float inv = rsqrtf(dx * dx + dy * dy + dz * dz);
        const float vx = dx * inv, vy = dy * inv, vz = dz * inv;
        const float tval = NEARV + (FARV - NEARV) * ((float)s + 0.5f) / (float)N_SAMPLES;
        float px = rays_o[ray * 3 + 0] + vx * tval;
        float py = rays_o[ray * 3 + 1] + vy * tval;
        float pz = rays_o[ray * 3 + 2] + vz * tval;
        const float nrm = fmaxf(fabsf(px), fmaxf(fabsf(py), fabsf(pz)));
        if (nrm > 1.0f) {
            const float invn = 1.0f / nrm;
            const float sc = (1.2f - 0.2f * invn) * invn;
            px *= sc; py *= sc; pz *= sc;
        }
        float gx = (px - XYZ_MIN) * COORD_SCALE;
        float gy = (py - XYZ_MIN) * COORD_SCALE;
        float gz = (pz - XYZ_MIN) * COORD_SCALE;
        gx = fminf(fmaxf(gx, 0.0f), 159.0f);
        gy = fminf(fmaxf(gy, 0.0f), 159.0f);
        gz = fminf(fmaxf(gz, 0.0f), 159.0f);
        const int ix = min((int)floorf(gx), 158);
        const int iy = min((int)floorf(gy), 158);
        const int iz = min((int)floorf(gz), 158);
        const float fx = gx - (float)ix, fy = gy - (float)iy, fz = gz - (float)iz;
        const float ex = 1.0f - fx, ey = 1.0f - fy;
        const int base = ix * GRID_D2 + iy * GRID_D + iz;
        wxy0 = ex * ey; wxy1 = ex * fy; wxy2 = fx * ey; wxy3 = fx * fy;
        ezr = 1.0f - fz; fzr = fz;
        const int vb[4] = {base, base + GRID_D, base + GRID_D2, base + GRID_D2 + GRID_D};
#pragma unroll
        for (int p = 0; p < 4; p++) {
            const char* src = (const char*)(PG + vb[p]);
            CP_ASYNC16(gdst0 + (uint32_t)(2 * p) * 3072u, src);
            CP_ASYNC16(gdst0 + (uint32_t)(2 * p + 1) * 3072u, src + 16);
        }
    };

    issue(t);
    CP_COMMIT();
    __syncthreads();

    while (true) {
        // ---- stage this ray's hidden bias (fp32) ----
        if (tid < 128) sm[SM_HB + tid] = HB[t * 128 + tid];

        CP_WAIT0();

        // ---- decode gather buffer -> density + k0 features; alpha stays in reg ----
        float accd = 0.0f;
        __half2 acck[6];
#pragma unroll
        for (int j = 0; j < 6; j++) acck[j] = __float2half2_rn(0.0f);
        {
            const float wxy[4] = {wxy0, wxy1, wxy2, wxy3};
#pragma unroll
            for (int p = 0; p < 4; p++) {
                const uint4 q0 = gbuf[(2 * p) * BLOCK + tid];
                const uint4 q1 = gbuf[(2 * p + 1) * BLOCK + tid];
                const float wz0 = wxy[p] * ezr, wz1 = wxy[p] * fzr;
                accd += bflo(q0.x) * wz0 + bflo(q1.x) * wz1;
                const __half2 h0 = __float2half2_rn(wz0);
                const __half2 h1 = __float2half2_rn(wz1);
                acck[0] = __hfma2(e4m3x2_to_h2(q0.x >> 16), h0, acck[0]);
                acck[1] = __hfma2(e4m3x2_to_h2(q0.y), h0, acck[1]);
                acck[2] = __hfma2(e4m3x2_to_h2(q0.y >> 16), h0, acck[2]);
                acck[3] = __hfma2(e4m3x2_to_h2(q0.z), h0, acck[3]);
                acck[4] = __hfma2(e4m3x2_to_h2(q0.z >> 16), h0, acck[4]);
                acck[5] = __hfma2(e4m3x2_to_h2(q0.w), h0, acck[5]);
                acck[0] = __hfma2(e4m3x2_to_h2(q1.x >> 16), h1, acck[0]);
                acck[1] = __hfma2(e4m3x2_to_h2(q1.y), h1, acck[1]);
                acck[2] = __hfma2(e4m3x2_to_h2(q1.y >> 16), h1, acck[2]);
                acck[3] = __hfma2(e4m3x2_to_h2(q1.z), h1, acck[3]);
                acck[4] = __hfma2(e4m3x2_to_h2(q1.z >> 16), h1, acck[4]);
                acck[5] = __hfma2(e4m3x2_to_h2(q1.w), h1, acck[5]);
            }
        }
        float alpha_reg;
        {
            const float x = accd + ACT_SHIFT;
            const float sigma = fmaxf(x, 0.0f) + log1pf(__expf(-fabsf(x)));
            alpha_reg = 1.0f - __expf(-sigma * STEPDIST);
        }

        // ---- features -> F smem (rows warp-private): 12 k0 + zero pad to K=16 ----
        {
            uint32_t* F = smw + SM_F;
#pragma unroll
            for (int j = 0; j < 6; j++) {
                const float2 kc = __half22float2(acck[j]);
                F[tid * 12 + j] = pack_bf16x2(kc.x, kc.y);
            }
            F[tid * 12 + 6] = 0u;
            F[tid * 12 + 7] = 0u;
        }

        // ---- issue next ray's gather (flies under the MLP below) ----
        const int tcur = t;
        const int tn = t + GRID_P;
        const bool have_next = (tn < NTILES);
        if (have_next) {
            t = tn;
            issue(tn);
            CP_COMMIT();
        }

        __syncthreads();   // hb staged (F is warp-private)

        // ---- layer 0 (K=16, one k-step, C-init = hb): C -> layer-1 A fragments ----
        uint32_t af[2][4];
#pragma unroll
        for (int tt = 0; tt < 2; tt++) {
            const uint32_t addr = Fb +
                (((m0 + 16 * tt + ((amt & 1) << 3) + arow) * 12 + ((amt >> 1) << 2)) << 2);
            ldsm_x4(af[tt][0], af[tt][1], af[tt][2], af[tt][3], addr);
        }
        uint32_t a1f[2][8][4];
#pragma unroll
        for (int nt = 0; nt < 16; nt++) {
            const int n0 = nt * 8;
            const float hb0 = sm[SM_HB + n0 + 2 * q];
            const float hb1 = sm[SM_HB + n0 + 2 * q + 1];
            float C0[4] = {hb0, hb1, hb0, hb1};
            float C1[4] = {hb0, hb1, hb0, hb1};
            uint32_t b0r, b1r;
            ldsm_x2(b0r, b1r, W0b + (((n0 + lrow) * 12 + 4 * lmat) << 2));
            mma_bf16(C0, af[0][0], af[0][1], af[0][2], af[0][3], b0r, b1r);
            mma_bf16(C1, af[1][0], af[1][1], af[1][2], af[1][3], b0r, b1r);
            const int kk1 = nt >> 1;
            const int hi = (nt & 1) << 1;
            a1f[0][kk1][hi]     = pack_bf16x2(fmaxf(C0[0], 0.0f), fmaxf(C0[1], 0.0f));
            a1f[0][kk1][hi + 1] = pack_bf16x2(fmaxf(C0[2], 0.0f), fmaxf(C0[3], 0.0f));
            a1f[1][kk1][hi]     = pack_bf16x2(fmaxf(C1[0], 0.0f), fmaxf(C1[1], 0.0f));
            a1f[1][kk1][hi + 1] = pack_bf16x2(fmaxf(C1[2], 0.0f), fmaxf(C1[3], 0.0f));
        }

        // ---- layer 1 + fused layer 2 ----
        float acc[4][3];
#pragma unroll
        for (int i = 0; i < 4; i++)
#pragma unroll
            for (int c = 0; c < 3; c++) acc[i][c] = 0.0f;

        const float* W2s = sm + SM_W2;
#pragma unroll
        for (int nt = 0; nt < 16; nt++) {
            const int n0 = nt * 8;
            const float cb0 = sm[SM_B1 + n0 + 2 * q];
            const float cb1 = sm[SM_B1 + n0 + 2 * q + 1];
            float C0[4] = {cb0, cb1, cb0, cb1};
            float C1[4] = {cb0, cb1, cb0, cb1};
#pragma unroll
            for (int kp = 0; kp < 4; kp++) {
                uint32_t w0r, w1r, w2r, w3r;
                ldsm_x4(w0r, w1r, w2r, w3r,
                        W1b + (((n0 + arow) * 68 + 16 * kp + (amt << 2)) << 2));
                const int kk = 2 * kp;
                mma_bf16(C0, a1f[0][kk][0], a1f[0][kk][1], a1f[0][kk][2], a1f[0][kk][3], w0r, w1r);
                mma_bf16(C1, a1f[1][kk][0], a1f[1][kk][1], a1f[1][kk][2], a1f[1][kk][3], w0r, w1r);
                mma_bf16(C0, a1f[0][kk + 1][0], a1f[0][kk + 1][1], a1f[0][kk + 1][2], a1f[0][kk + 1][3], w2r, w3r);
                mma_bf16(C1, a1f[1][kk + 1][0], a1f[1][kk + 1][1], a1f[1][kk + 1][2], a1f[1][kk + 1][3], w2r, w3r);
            }
            const int col0 = n0 + 2 * q, col1 = col0 + 1;
            const float w20x = W2s[col0 * 3 + 0], w20y = W2s[col0 * 3 + 1], w20z = W2s[col0 * 3 + 2];
            const float w21x = W2s[col1 * 3 + 0], w21y = W2s[col1 * 3 + 1], w21z = W2s[col1 * 3 + 2];
            {
                const float h0 = fmaxf(C0[0], 0.0f), h1 = fmaxf(C0[1], 0.0f);
                const float h2 = fmaxf(C0[2], 0.0f), h3 = fmaxf(C0[3], 0.0f);
                acc[0][0] += h0 * w20x + h1 * w21x;
                acc[0][1] += h0 * w20y + h1 * w21y;
                acc[0][2] += h0 * w20z + h1 * w21z;
                acc[1][0] += h2 * w20x + h3 * w21x;
                acc[1][1] += h2 * w20y + h3 * w21y;
                acc[1][2] += h2 * w20z + h3 * w21z;
            }
            {
                const float h0 = fmaxf(C1[0], 0.0f), h1 = fmaxf(C1[1], 0.0f);
                const float h2 = fmaxf(C1[2], 0.0f), h3 = fmaxf(C1[3], 0.0f);
                acc[2][0] += h0 * w20x + h1 * w21x;
                acc[2][1] += h0 * w20y + h1 * w21y;
                acc[2][2] += h0 * w20z + h1 * w21z;
                acc[3][0] += h2 * w20x + h3 * w21x;
                acc[3][1] += h2 * w20y + h3 * w21y;
                acc[3][2] += h2 * w20z + h3 * w21z;
            }
        }

#pragma unroll
        for (int i = 0; i < 4; i++)
#pragma unroll
            for (int c = 0; c < 3; c++) {
                acc[i][c] += __shfl_xor_sync(0xFFFFFFFFu, acc[i][c], 1);
                acc[i][c] += __shfl_xor_sync(0xFFFFFFFFu, acc[i][c], 2);
            }

        // ---- rgb -> smem (rows of this warp) ----
        if (q == 0) {
            const float bb0 = sm[SM_B2 + 0], bb1 = sm[SM_B2 + 1], bb2 = sm[SM_B2 + 2];
            const int rows[4] = {m0 + g8, m0 + 8 + g8, m0 + 16 + g8, m0 + 24 + g8};
#pragma unroll
            for (int i = 0; i < 4; i++) {
                sm[SM_RGB0 + rows[i]] = 1.0f / (1.0f + __expf(-(acc[i][0] + bb0)));
                sm[SM_RGB1 + rows[i]] = 1.0f / (1.0f + __expf(-(acc[i][1] + bb1)));
                sm[SM_RGB2 + rows[i]] = 1.0f / (1.0f + __expf(-(acc[i][2] + bb2)));
            }
        }
        __syncthreads();

        // ---- fused composite: warp w scans samples [32w, 32w+32) ----
        {
            const float c0 = sm[SM_RGB0 + tid];
            const float c1 = sm[SM_RGB1 + tid];
            const float c2 = sm[SM_RGB2 + tid];
            float p = 1.0f - alpha_reg + 1e-10f;
#pragma unroll
            for (int d = 1; d < 32; d <<= 1) {
                const float up = __shfl_up_sync(0xFFFFFFFFu, p, d);
                if (lane >= d) p *= up;
            }
            float excl = __shfl_up_sync(0xFFFFFFFFu, p, 1);
            if (lane == 0) excl = 1.0f;
            const float w = alpha_reg * excl;
            float wsum = w;
            float a0 = w * c0, a1 = w * c1, a2 = w * c2;
#pragma unroll
            for (int d = 16; d > 0; d >>= 1) {
                wsum += __shfl_down_sync(0xFFFFFFFFu, wsum, d);
                a0 += __shfl_down_sync(0xFFFFFFFFu, a0, d);
                a1 += __shfl_down_sync(0xFFFFFFFFu, a1, d);
                a2 += __shfl_down_sync(0xFFFFFFFFu, a2, d);
            }
            const float Pw = __shfl_sync(0xFFFFFFFFu, p, 31);
            if (lane == 0) {
                sm[SM_PART + warp * 8 + 0] = wsum;
                sm[SM_PART + warp * 8 + 1] = a0;
                sm[SM_PART + warp * 8 + 2] = a1;
                sm[SM_PART + warp * 8 + 3] = a2;
                sm[SM_PART + warp * 8 + 4] = Pw;
            }
        }
        __syncthreads();

        if (tid == 0) {
            float T = 1.0f, WS = 0.0f, A0 = 0.0f, A1 = 0.0f, A2 = 0.0f;
#pragma unroll
            for (int w = 0; w < 6; w++) {
                WS += T * sm[SM_PART + w * 8 + 0];
                A0 += T * sm[SM_PART + w * 8 + 1];
                A1 += T * sm[SM_PART + w * 8 + 2];
                A2 += T * sm[SM_PART + w * 8 + 3];
                T *= sm[SM_PART + w * 8 + 4];
            }
            const float bg = 1.0f - WS;
            out[tcur * 3 + 0] = A0 + bg;
            out[tcur * 3 + 1] = A1 + bg;
            out[tcur * 3 + 2] = A2 + bg;
        }

        if (!have_next) break;
    }
}

extern "C" void kernel_launch(void* const* d_in, const int* in_sizes, int n_in,
                              void* d_out, int out_size)
{
    const float* rays_o = (const float*)d_in[0];
    const float* rays_d = (const float*)d_in[1];
    const float* dgrid  = (const float*)d_in[2];
    const float* k0grid = (const float*)d_in[3];
    const float* w0 = (const float*)d_in[4];
    const float* b0 = (const float*)d_in[5];
    const float* w1 = (const float*)d_in[6];
    const float* b1 = (const float*)d_in[7];
    const float* w2 = (const float*)d_in[8];
    const float* b2 = (const float*)d_in[9];
    float* out = (float*)d_out;

    cudaFuncSetAttribute(point_kernel,
                         cudaFuncAttributeMaxDynamicSharedMemorySize, SMEM_BYTES);

    pack_grid_kernel<<<(GRID_D3 + 255) / 256, 256>>>(dgrid, k0grid, w0, w1);
    hb_kernel<<<N_RAYS, 128>>>(rays_d, w0, b0);
    point_kernel<<<GRID_P, BLOCK, SMEM_BYTES>>>(rays_o, rays_d, w2, b1, b2, out);
}

// round 17
// speedup vs baseline: 1.1410x; 1.0245x over previous
#include <cuda_runtime.h>
#include <cuda_fp16.h>
#include <cstdint>
#include <math.h>

#define N_RAYS 4096
#define N_SAMPLES 192
#define GRID_D 160
#define GRID_D2 (160*160)
#define GRID_D3 (160*160*160)
#define K0_DIM 12
#define XYZ_MIN (-1.2f)
#define COORD_SCALE (159.0f / 2.4f)
#define ACT_SHIFT (-4.595119850134589f)
#define STEPDIST (2.8f / 192.0f)
#define NEARV 0.2f
#define FARV 3.0f

#define BLOCK 192                  /* one ray per tile */
#define NTILES N_RAYS              /* 4096 */
#define GRID_P 296                 /* 2 CTAs x 148 SMs persistent */

// ---------------- scratch ----------------
__device__ uint32_t PW0T[128 * 12];    // [n][kpair] bf16x2: words 0-5 = k0 weights, 6-11 = 0
__device__ uint32_t PW1T[128 * 68];    // [n][kpair] bf16x2, k<128 real
__device__ float HB[N_RAYS * 128];     // per-ray: b0 + W0_vd @ vd_emb  (2 MB)
// packed voxel: 16B = [density bf16 | k0[0..11] e4m3 | pad16]
__device__ uint4 PG[GRID_D3];          // 65.5 MB (L2-resident)

// ---------------- smem layout (4-byte word units) ----------------
#define SM_W0T  0                      /* 1536 */
#define SM_W1T  1536                   /* 8704 */
#define SM_F    10240                  /* 192*12 = 2304 */
#define SM_W2   12544                  /* 384 */
#define SM_B1   12928                  /* 128 */
#define SM_B2   13056                  /* 4 */
#define SM_HB   13060                  /* 128 */
#define SM_RGB0 13188                  /* 192 */
#define SM_RGB1 13380                  /* 192 */
#define SM_RGB2 13572                  /* 192 */
#define SM_PART 13764                  /* 6*8 = 48 */
#define SM_G    13812                  /* 8 x 192 x uint4 = 6144 words; byte 55248 %16==0 */
#define SM_WORDS (SM_G + 6144)
#define SMEM_BYTES (SM_WORDS * 4)      /* ~78 KB -> 2 CTAs/SM */

__device__ __forceinline__ uint32_t pack_bf16x2(float lo, float hi) {
    uint32_t u;
    asm("cvt.rn.bf16x2.f32 %0, %1, %2;" : "=r"(u) : "f"(hi), "f"(lo));
    return u;
}
__device__ __forceinline__ float bflo(uint32_t u) { return __uint_as_float(u << 16); }

__device__ __forceinline__ uint32_t pack_e4m3x2(float lo, float hi) {
    uint16_t r;
    asm("cvt.rn.satfinite.e4m3x2.f32 %0, %1, %2;" : "=h"(r) : "f"(hi), "f"(lo));
    return (uint32_t)r;
}
__device__ __forceinline__ __half2 e4m3x2_to_h2(uint32_t u) {
    uint32_t h2;
    asm("cvt.rn.f16x2.e4m3x2 %0, %1;" : "=r"(h2) : "h"((uint16_t)(u)));
    return *reinterpret_cast<__half2*>(&h2);
}

__device__ __forceinline__ uint32_t smem_u32(const void* p) {
    uint32_t a;
    asm("{ .reg .u64 t; cvta.to.shared.u64 t, %1; cvt.u32.u64 %0, t; }" : "=r"(a) : "l"(p));
    return a;
}
__device__ __forceinline__ void ldsm_x4(uint32_t& r0, uint32_t& r1, uint32_t& r2, uint32_t& r3,
                                        uint32_t addr) {
    asm volatile("ldmatrix.sync.aligned.m8n8.x4.shared.b16 {%0,%1,%2,%3}, [%4];"
                 : "=r"(r0), "=r"(r1), "=r"(r2), "=r"(r3) : "r"(addr));
}
__device__ __forceinline__ void ldsm_x2(uint32_t& r0, uint32_t& r1, uint32_t addr) {
    asm volatile("ldmatrix.sync.aligned.m8n8.x2.shared.b16 {%0,%1}, [%2];"
                 : "=r"(r0), "=r"(r1) : "r"(addr));
}
__device__ __forceinline__ void mma_bf16(float c[4],
                                         uint32_t a0, uint32_t a1, uint32_t a2, uint32_t a3,
                                         uint32_t b0, uint32_t b1) {
    asm volatile("mma.sync.aligned.m16n8k16.row.col.f32.bf16.bf16.f32 "
                 "{%0,%1,%2,%3}, {%4,%5,%6,%7}, {%8,%9}, {%0,%1,%2,%3};"
                 : "+f"(c[0]), "+f"(c[1]), "+f"(c[2]), "+f"(c[3])
                 : "r"(a0), "r"(a1), "r"(a2), "r"(a3), "r"(b0), "r"(b1));
}
#define CP_ASYNC16(dst, src) \
    asm volatile("cp.async.cg.shared.global [%0], [%1], 16;" :: "r"(dst), "l"(src))
#define CP_COMMIT() asm volatile("cp.async.commit_group;" ::: "memory")
#define CP_WAIT0()  asm volatile("cp.async.wait_group 0;" ::: "memory")

// ---------------- pack grids + weight prep + per-ray hb (one launch) ----------------
__global__ void __launch_bounds__(256)
pack_grid_kernel(const float* __restrict__ dgrid, const float* __restrict__ k0grid,
                 const float* __restrict__ w0, const float* __restrict__ w1,
                 const float* __restrict__ rays_d, const float* __restrict__ b0)
{
    const int gid = blockIdx.x * blockDim.x + threadIdx.x;
    if (gid < 128 * 12) {
        const int n = gid / 12, wd = gid - n * 12;
        const int k = 2 * wd;
        const float lo = (k < 12) ? w0[k * 128 + n] : 0.0f;
        const float hi = (k + 1 < 12) ? w0[(k + 1) * 128 + n] : 0.0f;
        PW0T[gid] = pack_bf16x2(lo, hi);
    } else if (gid < 128 * 12 + 128 * 68) {
        const int i = gid - 128 * 12;
        const int n = i / 68, wd = i - n * 68;
        const int k = 2 * wd;
        const float lo = (k < 128) ? w1[k * 128 + n] : 0.0f;
        const float hi = (k + 1 < 128) ? w1[(k + 1) * 128 + n] : 0.0f;
        PW1T[i] = pack_bf16x2(lo, hi);
    } else if (gid < 128 * 12 + 128 * 68 + N_RAYS * 128) {
        // per-ray hidden bias: hb[r][n] = b0[n] + sum_k vd_emb[r][k] * W0[12+k][n]
        const int i = gid - (128 * 12 + 128 * 68);
        const int r = i >> 7;
        const int n = i & 127;
        const float dx = rays_d[r * 3 + 0], dy = rays_d[r * 3 + 1], dz = rays_d[r * 3 + 2];
        const float inv = rsqrtf(dx * dx + dy * dy + dz * dz);
        const float vx = dx * inv, vy = dy * inv, vz = dz * inv;
        float vd[27];
        vd[0] = vx; vd[1] = vy; vd[2] = vz;
        const float v3[3] = {vx, vy, vz};
#pragma unroll
        for (int ii = 0; ii < 3; ii++) {
#pragma unroll
            for (int p = 0; p < 4; p++) {
                float sv, cv;
                __sincosf(v3[ii] * (float)(1 << p), &sv, &cv);
                vd[3 + ii * 4 + p] = sv;
                vd[15 + ii * 4 + p] = cv;
            }
        }
        float acc = b0[n];
#pragma unroll
        for (int k = 0; k < 27; k++) acc += vd[k] * w0[(12 + k) * 128 + n];
        HB[r * 128 + n] = acc;
    }
    const int v = gid;
    if (v >= GRID_D3) return;
    const float d = dgrid[v];
    float k[12];
#pragma unroll
    for (int c = 0; c < K0_DIM; c++) k[c] = k0grid[c * GRID_D3 + v];
    const uint32_t dbf = pack_bf16x2(d, 0.0f) & 0xffffu;
    const uint32_t a = dbf | (pack_e4m3x2(k[0], k[1]) << 16);
    const uint32_t b = pack_e4m3x2(k[2], k[3]) | (pack_e4m3x2(k[4], k[5]) << 16);
    const uint32_t c = pack_e4m3x2(k[6], k[7]) | (pack_e4m3x2(k[8], k[9]) << 16);
    const uint32_t e = pack_e4m3x2(k[10], k[11]);
    PG[v] = make_uint4(a, b, c, e);
}

// ---------------- persistent point+composite kernel: 1 ray / tile ----------------
__global__ void __launch_bounds__(BLOCK, 2)
point_kernel(const float* __restrict__ rays_o,
             const float* __restrict__ rays_d,
             const float* __restrict__ w2,
             const float* __restrict__ b1,
             const float* __restrict__ b2,
             float* __restrict__ out)
{
    extern __shared__ float sm[];
    uint32_t* smw = (uint32_t*)sm;
    const int tid = threadIdx.x;
    const uint32_t sm_base = smem_u32(sm);
    const uint32_t gdst0 = sm_base + SM_G * 4 + (uint32_t)tid * 16;

    // ---- stage static weights ONCE per CTA ----
    {
        float4* d0 = (float4*)(smw + SM_W0T);
        const float4* s0 = (const float4*)PW0T;
        for (int i = tid; i < 384; i += BLOCK) d0[i] = s0[i];
        float4* d1 = (float4*)(smw + SM_W1T);
        const float4* s1 = (const float4*)PW1T;
        for (int i = tid; i < 2176; i += BLOCK) d1[i] = s1[i];
    }
    for (int i = tid; i < 384; i += BLOCK) sm[SM_W2 + i] = w2[i];
    if (tid < 128) sm[SM_B1 + tid] = b1[tid];
    if (tid < 3) sm[SM_B2 + tid] = b2[tid];

    const int lane = tid & 31;
    const int warp = tid >> 5;                 // 0..5
    const int g8 = lane >> 2;
    const int q = lane & 3;
    const int m0 = warp * 32;
    const int arow = lane & 7;
    const int amt = lane >> 3;
    const int lrow = lane & 7;
    const int lmat = (lane >> 3) & 1;
    const uint32_t Fb  = sm_base + SM_F * 4;
    const uint32_t W0b = sm_base + SM_W0T * 4;
    const uint32_t W1b = sm_base + SM_W1T * 4;
    const uint4* gbuf = (const uint4*)(smw + SM_G);

    float wxy0, wxy1, wxy2, wxy3, ezr, fzr;
    int t = blockIdx.x;

    auto issue = [&](int ray) {
        const int s = tid;
        float dx = rays_d[ray * 3 + 0], dy = rays_d[ray * 3 + 1], dz = rays_d[ray * 3 + 2];
        const float inv = rsqrtf(dx * dx + dy * dy + dz * dz);
        const float vx = dx * inv, vy = dy * inv, vz = dz * inv;
        const float tval = NEARV + (FARV - NEARV) * ((float)s + 0.5f) / (float)N_SAMPLES;
        float px = rays_o[ray * 3 + 0] + vx * tval;
        float py = rays_o[ray * 3 + 1] + vy * tval;
        float pz = rays_o[ray * 3 + 2] + vz * tval;
        const float nrm = fmaxf(fabsf(px), fmaxf(fabsf(py), fabsf(pz)));
        if (nrm > 1.0f) {
            const float invn = 1.0f / nrm;
            const float sc = (1.2f - 0.2f * invn) * invn;
            px *= sc; py *= sc; pz *= sc;
        }
        float gx = (px - XYZ_MIN) * COORD_SCALE;
        float gy = (py - XYZ_MIN) * COORD_SCALE;
        float gz = (pz - XYZ_MIN) * COORD_SCALE;
        gx = fminf(fmaxf(gx, 0.0f), 159.0f);
        gy = fminf(fmaxf(gy, 0.0f), 159.0f);
        gz = fminf(fmaxf(gz, 0.0f), 159.0f);
        const int ix = min((int)floorf(gx), 158);
        const int iy = min((int)floorf(gy), 158);
        const int iz = min((int)floorf(gz), 158);
        const float fx = gx - (float)ix, fy = gy - (float)iy, fz = gz - (float)iz;
        const float ex = 1.0f - fx, ey = 1.0f - fy;
        const int base = ix * GRID_D2 + iy * GRID_D + iz;
        wxy0 = ex * ey; wxy1 = ex * fy; wxy2 = fx * ey; wxy3 = fx * fy;
        ezr = 1.0f - fz; fzr = fz;
        const int vb[4] = {base, base + GRID_D, base + GRID_D2, base + GRID_D2 + GRID_D};
#pragma unroll
        for (int p = 0; p < 4; p++) {
            const char* src = (const char*)(PG + vb[p]);
            CP_ASYNC16(gdst0 + (uint32_t)(2 * p) * 3072u, src);
            CP_ASYNC16(gdst0 + (uint32_t)(2 * p + 1) * 3072u, src + 16);
        }
    };

    issue(t);
    CP_COMMIT();
    __syncthreads();

    while (true) {
        // ---- stage this ray's hidden bias (fp32) ----
        if (tid < 128) sm[SM_HB + tid] = HB[t * 128 + tid];

        CP_WAIT0();

        // ---- decode gather buffer -> density + k0 features; alpha stays in reg ----
        float accd = 0.0f;
        __half2 acck[6];
#pragma unroll
        for (int j = 0; j < 6; j++) acck[j] = __float2half2_rn(0.0f);
        {
            const float wxy[4] = {wxy0, wxy1, wxy2, wxy3};
#pragma unroll
            for (int p = 0; p < 4; p++) {
                const uint4 q0 = gbuf[(2 * p) * BLOCK + tid];
                const uint4 q1 = gbuf[(2 * p + 1) * BLOCK + tid];
                const float wz0 = wxy[p] * ezr, wz1 = wxy[p] * fzr;
                accd += bflo(q0.x) * wz0 + bflo(q1.x) * wz1;
                const __half2 h0 = __float2half2_rn(wz0);
                const __half2 h1 = __float2half2_rn(wz1);
                acck[0] = __hfma2(e4m3x2_to_h2(q0.x >> 16), h0, acck[0]);
                acck[1] = __hfma2(e4m3x2_to_h2(q0.y), h0, acck[1]);
                acck[2] = __hfma2(e4m3x2_to_h2(q0.y >> 16), h0, acck[2]);
                acck[3] = __hfma2(e4m3x2_to_h2(q0.z), h0, acck[3]);
                acck[4] = __hfma2(e4m3x2_to_h2(q0.z >> 16), h0, acck[4]);
                acck[5] = __hfma2(e4m3x2_to_h2(q0.w), h0, acck[5]);
                acck[0] = __hfma2(e4m3x2_to_h2(q1.x >> 16), h1, acck[0]);
                acck[1] = __hfma2(e4m3x2_to_h2(q1.y), h1, acck[1]);
                acck[2] = __hfma2(e4m3x2_to_h2(q1.y >> 16), h1, acck[2]);
                acck[3] = __hfma2(e4m3x2_to_h2(q1.z), h1, acck[3]);
                acck[4] = __hfma2(e4m3x2_to_h2(q1.z >> 16), h1, acck[4]);
                acck[5] = __hfma2(e4m3x2_to_h2(q1.w), h1, acck[5]);
            }
        }
        float alpha_reg;
        {
            const float x = accd + ACT_SHIFT;
            const float sigma = fmaxf(x, 0.0f) + log1pf(__expf(-fabsf(x)));
            alpha_reg = 1.0f - __expf(-sigma * STEPDIST);
        }

        // ---- features -> F smem (rows warp-private): 12 k0 + zero pad to K=16 ----
        {
            uint32_t* F = smw + SM_F;
#pragma unroll
            for (int j = 0; j < 6; j++) {
                const float2 kc = __half22float2(acck[j]);
                F[tid * 12 + j] = pack_bf16x2(kc.x, kc.y);
            }
            F[tid * 12 + 6] = 0u;
            F[tid * 12 + 7] = 0u;
        }

        // ---- issue next ray's gather (flies under the MLP below) ----
        const int tcur = t;
        const int tn = t + GRID_P;
        const bool have_next = (tn < NTILES);
        if (have_next) {
            t = tn;
            issue(tn);
            CP_COMMIT();
        }

        __syncthreads();   // hb staged (F is warp-private)

        // ---- layer 0 (K=16, one k-step, C-init = hb): C -> layer-1 A fragments ----
        uint32_t af[2][4];
#pragma unroll
        for (int tt = 0; tt < 2; tt++) {
            const uint32_t addr = Fb +
                (((m0 + 16 * tt + ((amt & 1) << 3) + arow) * 12 + ((amt >> 1) << 2)) << 2);
            ldsm_x4(af[tt][0], af[tt][1], af[tt][2], af[tt][3], addr);
        }
        uint32_t a1f[2][8][4];
#pragma unroll
        for (int nt = 0; nt < 16; nt++) {
            const int n0 = nt * 8;
            const float hb0 = sm[SM_HB + n0 + 2 * q];
            const float hb1 = sm[SM_HB + n0 + 2 * q + 1];
            float C0[4] = {hb0, hb1, hb0, hb1};
            float C1[4] = {hb0, hb1, hb0, hb1};
            uint32_t b0r, b1r;
            ldsm_x2(b0r, b1r, W0b + (((n0 + lrow) * 12 + 4 * lmat) << 2));
            mma_bf16(C0, af[0][0], af[0][1], af[0][2], af[0][3], b0r, b1r);
            mma_bf16(C1, af[1][0], af[1][1], af[1][2], af[1][3], b0r, b1r);
            const int kk1 = nt >> 1;
            const int hi = (nt & 1) << 1;
            a1f[0][kk1][hi]     = pack_bf16x2(fmaxf(C0[0], 0.0f), fmaxf(C0[1], 0.0f));
            a1f[0][kk1][hi + 1] = pack_bf16x2(fmaxf(C0[2], 0.0f), fmaxf(C0[3], 0.0f));
            a1f[1][kk1][hi]     = pack_bf16x2(fmaxf(C1[0], 0.0f), fmaxf(C1[1], 0.0f));
            a1f[1][kk1][hi + 1] = pack_bf16x2(fmaxf(C1[2], 0.0f), fmaxf(C1[3], 0.0f));
        }

        // ---- layer 1 + fused layer 2 ----
        float acc[4][3];
#pragma unroll
        for (int i = 0; i < 4; i++)
#pragma unroll
            for (int c = 0; c < 3; c++) acc[i][c] = 0.0f;

        const float* W2s = sm + SM_W2;
#pragma unroll
        for (int nt = 0; nt < 16; nt++) {
            const int n0 = nt * 8;
            const float cb0 = sm[SM_B1 + n0 + 2 * q];
            const float cb1 = sm[SM_B1 + n0 + 2 * q + 1];
            float C0[4] = {cb0, cb1, cb0, cb1};
            float C1[4] = {cb0, cb1, cb0, cb1};
#pragma unroll
            for (int kp = 0; kp < 4; kp++) {
                uint32_t w0r, w1r, w2r, w3r;
                ldsm_x4(w0r, w1r, w2r, w3r,
                        W1b + (((n0 + arow) * 68 + 16 * kp + (amt << 2)) << 2));
                const int kk = 2 * kp;
                mma_bf16(C0, a1f[0][kk][0], a1f[0][kk][1], a1f[0][kk][2], a1f[0][kk][3], w0r, w1r);
                mma_bf16(C1, a1f[1][kk][0], a1f[1][kk][1], a1f[1][kk][2], a1f[1][kk][3], w0r, w1r);
                mma_bf16(C0, a1f[0][kk + 1][0], a1f[0][kk + 1][1], a1f[0][kk + 1][2], a1f[0][kk + 1][3], w2r, w3r);
                mma_bf16(C1, a1f[1][kk + 1][0], a1f[1][kk + 1][1], a1f[1][kk + 1][2], a1f[1][kk + 1][3], w2r, w3r);
            }
            const int col0 = n0 + 2 * q, col1 = col0 + 1;
            const float w20x = W2s[col0 * 3 + 0], w20y = W2s[col0 * 3 + 1], w20z = W2s[col0 * 3 + 2];
            const float w21x = W2s[col1 * 3 + 0], w21y = W2s[col1 * 3 + 1], w21z = W2s[col1 * 3 + 2];
            {
                const float h0 = fmaxf(C0[0], 0.0f), h1 = fmaxf(C0[1], 0.0f);
                const float h2 = fmaxf(C0[2], 0.0f), h3 = fmaxf(C0[3], 0.0f);
                acc[0][0] += h0 * w20x + h1 * w21x;
                acc[0][1] += h0 * w20y + h1 * w21y;
                acc[0][2] += h0 * w20z + h1 * w21z;
                acc[1][0] += h2 * w20x + h3 * w21x;
                acc[1][1] += h2 * w20y + h3 * w21y;
                acc[1][2] += h2 * w20z + h3 * w21z;
            }
            {
                const float h0 = fmaxf(C1[0], 0.0f), h1 = fmaxf(C1[1], 0.0f);
                const float h2 = fmaxf(C1[2], 0.0f), h3 = fmaxf(C1[3], 0.0f);
                acc[2][0] += h0 * w20x + h1 * w21x;
                acc[2][1] += h0 * w20y + h1 * w21y;
                acc[2][2] += h0 * w20z + h1 * w21z;
                acc[3][0] += h2 * w20x + h3 * w21x;
                acc[3][1] += h2 * w20y + h3 * w21y;
                acc[3][2] += h2 * w20z + h3 * w21z;
            }
        }

#pragma unroll
        for (int i = 0; i < 4; i++)
#pragma unroll
            for (int c = 0; c < 3; c++) {
                acc[i][c] += __shfl_xor_sync(0xFFFFFFFFu, acc[i][c], 1);
                acc[i][c] += __shfl_xor_sync(0xFFFFFFFFu, acc[i][c], 2);
            }

        // ---- rgb -> smem rows of this warp (warp-private: rows m0..m0+31) ----
        if (q == 0) {
            const float bb0 = sm[SM_B2 + 0], bb1 = sm[SM_B2 + 1], bb2 = sm[SM_B2 + 2];
            const int rows[4] = {m0 + g8, m0 + 8 + g8, m0 + 16 + g8, m0 + 24 + g8};
#pragma unroll
            for (int i = 0; i < 4; i++) {
                sm[SM_RGB0 + rows[i]] = 1.0f / (1.0f + __expf(-(acc[i][0] + bb0)));
                sm[SM_RGB1 + rows[i]] = 1.0f / (1.0f + __expf(-(acc[i][1] + bb1)));
                sm[SM_RGB2 + rows[i]] = 1.0f / (1.0f + __expf(-(acc[i][2] + bb2)));
            }
        }
        __syncwarp();   // composite below reads ONLY this warp's rows

        // ---- fused composite: warp w scans samples [32w, 32w+32) ----
        {
            const float c0 = sm[SM_RGB0 + tid];
            const float c1 = sm[SM_RGB1 + tid];
            const float c2 = sm[SM_RGB2 + tid];
            float p = 1.0f - alpha_reg + 1e-10f;
#pragma unroll
            for (int d = 1; d < 32; d <<= 1) {
                const float up = __shfl_up_sync(0xFFFFFFFFu, p, d);
                if (lane >= d) p *= up;
            }
            float excl = __shfl_up_sync(0xFFFFFFFFu, p, 1);
            if (lane == 0) excl = 1.0f;
            const float w = alpha_reg * excl;
            float wsum = w;
            float a0 = w * c0, a1 = w * c1, a2 = w * c2;
#pragma unroll
            for (int d = 16; d > 0; d >>= 1) {
                wsum += __shfl_down_sync(0xFFFFFFFFu, wsum, d);
                a0 += __shfl_down_sync(0xFFFFFFFFu, a0, d);
                a1 += __shfl_down_sync(0xFFFFFFFFu, a1, d);
                a2 += __shfl_down_sync(0xFFFFFFFFu, a2, d);
            }
            const float Pw = __shfl_sync(0xFFFFFFFFu, p, 31);
            if (lane == 0) {
                sm[SM_PART + warp * 8 + 0] = wsum;
                sm[SM_PART + warp * 8 + 1] = a0;
                sm[SM_PART + warp * 8 + 2] = a1;
                sm[SM_PART + warp * 8 + 3] = a2;
                sm[SM_PART + warp * 8 + 4] = Pw;
            }
        }
        __syncthreads();

        if (tid == 0) {
            float T = 1.0f, WS = 0.0f, A0 = 0.0f, A1 = 0.0f, A2 = 0.0f;
#pragma unroll
            for (int w = 0; w < 6; w++) {
                WS += T * sm[SM_PART + w * 8 + 0];
                A0 += T * sm[SM_PART + w * 8 + 1];
                A1 += T * sm[SM_PART + w * 8 + 2];
                A2 += T * sm[SM_PART + w * 8 + 3];
                T *= sm[SM_PART + w * 8 + 4];
            }
            const float bg = 1.0f - WS;
            out[tcur * 3 + 0] = A0 + bg;
            out[tcur * 3 + 1] = A1 + bg;
            out[tcur * 3 + 2] = A2 + bg;
        }

        if (!have_next) break;
    }
}

extern "C" void kernel_launch(void* const* d_in, const int* in_sizes, int n_in,
                              void* d_out, int out_size)
{
    const float* rays_o = (const float*)d_in[0];
    const float* rays_d = (const float*)d_in[1];
    const float* dgrid  = (const float*)d_in[2];
    const float* k0grid = (const float*)d_in[3];
    const float* w0 = (const float*)d_in[4];
    const float* b0 = (const float*)d_in[5];
    const float* w1 = (const float*)d_in[6];
    const float* b1 = (const float*)d_in[7];
    const float* w2 = (const float*)d_in[8];
    const float* b2 = (const float*)d_in[9];
    float* out = (float*)d_out;

    cudaFuncSetAttribute(point_kernel,
                         cudaFuncAttributeMaxDynamicSharedMemorySize, SMEM_BYTES);

    pack_grid_kernel<<<(GRID_D3 + 255) / 256, 256>>>(dgrid, k0grid, w0, w1, rays_d, b0);
    point_kernel<<<GRID_P, BLOCK, SMEM_BYTES>>>(rays_o, rays_d, w2, b1, b2, out);
}